// round 4
// baseline (speedup 1.0000x reference)
#include <cuda_runtime.h>
#include <cuda_bf16.h>
#include <cstdint>

#define DINLINE __device__ __forceinline__

// ======================= scratch (device globals) =======================
__device__ __align__(16) float g_X [64*132*132*3];
__device__ __align__(16) float g_O1[64*65*65*200];
__device__ __align__(16) float g_O2[64*31*31*400];
__device__ __align__(16) float g_O3[64*15*15*800];
__device__ float g_W4t[7200*10];

// A: [Npad][2*PK]  (Ah | Al),  B: [OCpad][3*PK]  (Wh | Wl | Wh)
// L1: PK=64   Npad=270592 OCpad=256
// L2: PK=1856 Npad=61696  OCpad=512
// L3: PK=3648 Npad=14592  OCpad=896
__device__ __align__(16) __nv_bfloat16 g_A1[(size_t)270592*128];
__device__ __align__(16) __nv_bfloat16 g_A2[(size_t)61696*3712];
__device__ __align__(16) __nv_bfloat16 g_A3[(size_t)14592*7296];
__device__ __align__(16) __nv_bfloat16 g_B1[(size_t)256*192];
__device__ __align__(16) __nv_bfloat16 g_B2[(size_t)512*5568];
__device__ __align__(16) __nv_bfloat16 g_B3[(size_t)896*10944];

// ======================= helpers =======================
DINLINE uint32_t smem_u32(const void* p){
    uint32_t a;
    asm("{ .reg .u64 t; cvta.to.shared.u64 t, %1; cvt.u32.u64 %0, t; }" : "=r"(a) : "l"(p));
    return a;
}
DINLINE void cp16(uint32_t dst, const void* src){
    asm volatile("cp.async.cg.shared.global [%0], [%1], 16;" :: "r"(dst), "l"(src));
}
DINLINE void cp_commit(){ asm volatile("cp.async.commit_group;" ::: "memory"); }
DINLINE void cp_wait1(){ asm volatile("cp.async.wait_group 1;" ::: "memory"); }

DINLINE void ldmx4(uint32_t r[4], uint32_t addr){
    asm volatile("ldmatrix.sync.aligned.m8n8.x4.shared.b16 {%0,%1,%2,%3}, [%4];"
        : "=r"(r[0]), "=r"(r[1]), "=r"(r[2]), "=r"(r[3]) : "r"(addr));
}
DINLINE void mma_bf16(float c[4], const uint32_t a[4], uint32_t b0, uint32_t b1){
    asm volatile("mma.sync.aligned.m16n8k16.row.col.f32.bf16.bf16.f32 "
        "{%0,%1,%2,%3}, {%4,%5,%6,%7}, {%8,%9}, {%0,%1,%2,%3};"
        : "+f"(c[0]), "+f"(c[1]), "+f"(c[2]), "+f"(c[3])
        : "r"(a[0]), "r"(a[1]), "r"(a[2]), "r"(a[3]), "r"(b0), "r"(b1));
}

// ======================= layout transforms =======================
__global__ void k_nchw2nhwc(const float* __restrict__ in, float* __restrict__ out,
                            int B, int C, int H, int W) {
    int idx = blockIdx.x * blockDim.x + threadIdx.x;
    if (idx >= B * C * H * W) return;
    int c = idx % C;
    int t = idx / C;
    int x = t % W; t /= W;
    int y = t % H; t /= H;
    out[idx] = in[((t * C + c) * H + y) * W + x];
}

__global__ void k_wt(const float* __restrict__ w, float* __restrict__ wt, int OC, int IC) {
    int idx = blockIdx.x * blockDim.x + threadIdx.x;
    if (idx >= OC * IC * 9) return;
    int oc  = idx % OC;
    int k   = idx / OC;
    int ic  = k % IC;
    int tap = k / IC;
    wt[idx] = w[(oc * IC + ic) * 9 + tap];
}

// W[oc][ic][3][3] -> B[ocpad][3*PK] bf16 blocks (Wh | Wl | Wh)
__global__ void k_wsplit(const float* __restrict__ W, __nv_bfloat16* __restrict__ Bw,
                         int OC, int IC, int Klayer, int PK, int OCpad)
{
    long idx = (long)blockIdx.x*blockDim.x + threadIdx.x;
    long total = (long)OCpad * 3 * PK;
    if (idx >= total) return;
    int ldb = 3 * PK;
    int oc = (int)(idx / ldb);
    int k2 = (int)(idx - (long)oc*ldb);
    int blk = k2 / PK, kk = k2 - blk*PK;
    __nv_bfloat16 out = __float2bfloat16(0.f);
    if (oc < OC && kk < Klayer){
        int tap = kk/IC, c = kk - tap*IC;
        float x = W[((size_t)oc*IC + c)*9 + tap];
        __nv_bfloat16 h = __float2bfloat16(x);
        out = (blk == 1) ? __float2bfloat16(x - __bfloat162float(h)) : h;
    }
    Bw[idx] = out;
}

// layers 2/3 gather: A[n][2*PK] = (Ah | Al). IC % 8 == 0.
__global__ void k_gather(const float* __restrict__ In, __nv_bfloat16* __restrict__ A,
                         const int* __restrict__ selh, const int* __restrict__ selw,
                         int IH, int IW, int IC, int OW, int P, int stride,
                         int Klayer, int PK, int Nreal, int Npad)
{
    int vecs = PK >> 3;
    long idx = (long)blockIdx.x*blockDim.x + threadIdx.x;
    if (idx >= (long)Npad * vecs) return;
    int n = (int)(idx / vecs);
    int v = (int)(idx - (long)n*vecs);
    int kk = v << 3;
    __nv_bfloat16 h[8], l[8];
    if (n < Nreal && kk < Klayer){
        int b = n / P, p = n - b*P;
        int oy = p / OW, ox = p - oy*OW;
        int ph = oy*stride + selh[p], pw = ox*stride + selw[p];
        int tap = kk / IC, c = kk - tap*IC;
        int ky = tap/3, kx = tap - ky*3;
        const float* src = In + ((size_t)((b*IH+ph+ky)*IW) + (pw+kx))*IC + c;
        float x[8];
        *(float4*)&x[0] = *(const float4*)src;
        *(float4*)&x[4] = *(const float4*)(src+4);
#pragma unroll
        for (int i=0;i<8;i++){
            __nv_bfloat16 hh = __float2bfloat16(x[i]);
            h[i] = hh;
            l[i] = __float2bfloat16(x[i] - __bfloat162float(hh));
        }
    } else {
#pragma unroll
        for (int i=0;i<8;i++){ h[i]=__float2bfloat16(0.f); l[i]=h[i]; }
    }
    __nv_bfloat16* row = A + (size_t)n * (2*PK);
    *(uint4*)(row + kk)      = *(uint4*)h;
    *(uint4*)(row + PK + kk) = *(uint4*)l;
}

// layer 1: IC=3, K=27, PK=64; A row = 128 cols (Ah|Al)
__global__ void k_gather1(const float* __restrict__ X, __nv_bfloat16* __restrict__ A,
                          const int* __restrict__ selh, const int* __restrict__ selw)
{
    int n = blockIdx.x*blockDim.x + threadIdx.x;
    if (n >= 270592) return;
    __nv_bfloat16 row[128];
#pragma unroll
    for (int i=0;i<128;i++) row[i] = __float2bfloat16(0.f);
    if (n < 270400){
        int b = n / 4225, p = n - b*4225;
        int oy = p/65, ox = p - oy*65;
        int ph = oy*2 + selh[p], pw = ox*2 + selw[p];
        const float* base = X + ((size_t)(b*132+ph)*132 + pw)*3;
#pragma unroll
        for (int ky=0;ky<3;ky++){
#pragma unroll
            for (int t=0;t<9;t++){
                float x = base[ky*396 + t];
                int k = ky*9 + t;
                __nv_bfloat16 h = __float2bfloat16(x);
                row[k]      = h;
                row[64 + k] = __float2bfloat16(x - __bfloat162float(h));
            }
        }
    }
    uint4* dst = (uint4*)(A + (size_t)n*128);
    uint4* s = (uint4*)row;
#pragma unroll
    for (int i=0;i<16;i++) dst[i] = s[i];
}

// ======================= HMMA GEMM =======================
// CTA tile 256(n) x 128(oc), BK=64 bf16, 512 threads (16 warps, 8x2).
// 3-stage ring, stage = A 32KB + B 16KB = 48KB; one barrier per chunk.
static constexpr int STAGE = 49152;
static constexpr int SMEM_HM = 3 * STAGE;

DINLINE void stage_load(const __nv_bfloat16* __restrict__ Ag,
                        const __nv_bfloat16* __restrict__ Bg,
                        long ldA, long ldB, int Acol, int Bcol,
                        uint32_t sA, uint32_t sB, int tid)
{
#pragma unroll
    for (int i=0;i<4;i++){
        int q = tid + i*512;            // 2048 chunks: 256 rows x 8
        int row = q>>3, ch = q&7;
        cp16(sA + row*128 + ((ch ^ (row&7))<<4),
             Ag + (size_t)row*ldA + Acol + ch*8);
    }
#pragma unroll
    for (int i=0;i<2;i++){
        int q = tid + i*512;            // 1024 chunks: 128 rows x 8
        int row = q>>3, ch = q&7;
        cp16(sB + row*128 + ((ch ^ (row&7))<<4),
             Bg + (size_t)row*ldB + Bcol + ch*8);
    }
}

__global__ __launch_bounds__(512, 1)
void k_hmma(const __nv_bfloat16* __restrict__ A, const __nv_bfloat16* __restrict__ B,
            const float* __restrict__ bias, const int* __restrict__ mask,
            float* __restrict__ Out,
            int PK, int PKc, int OC, int P, int Nreal, int relu)
{
    extern __shared__ char smem[];
    const uint32_t sb = smem_u32(smem);
    const int tid = threadIdx.x, lane = tid & 31, warp = tid >> 5;
    const int wm = warp >> 1, wn = warp & 1;   // 8 x 2 warp grid; warp tile 32 x 64

    const long ldA = 2L*PK, ldB = 3L*PK;
    const __nv_bfloat16* Ag = A + (size_t)(blockIdx.y*256) * ldA;
    const __nv_bfloat16* Bg = B + (size_t)(blockIdx.x*128) * ldB;
    const int NC = 3 * PKc;

    float c[2][8][4];
#pragma unroll
    for (int i=0;i<2;i++)
#pragma unroll
        for (int j=0;j<8;j++)
#pragma unroll
            for (int k=0;k<4;k++) c[i][j][k] = 0.f;

    // prologue: chunks 0,1
    stage_load(Ag, Bg, ldA, ldB, 0, 0, sb, sb + 32768, tid);
    cp_commit();
    if (NC > 1){
        int blk = 1 / PKc, ci = 1 - blk*PKc;
        int ac = (blk==2 ? PK : 0) + ci*64;
        stage_load(Ag, Bg, ldA, ldB, ac, 64, sb + STAGE, sb + STAGE + 32768, tid);
    }
    cp_commit();

#pragma unroll 1
    for (int cc = 0; cc < NC; cc++){
        cp_wait1();                 // chunk cc resident
        __syncthreads();            // all warps past compute(cc-1); cc visible
        if (cc + 2 < NC){           // prefetch chunk cc+2 into stage (cc+2)%3
            int c2 = cc + 2;
            int blk = c2 / PKc, ci = c2 - blk*PKc;
            int ac = (blk==2 ? PK : 0) + ci*64;
            int s2 = c2 % 3;
            stage_load(Ag, Bg, ldA, ldB, ac, c2*64, sb + s2*STAGE, sb + s2*STAGE + 32768, tid);
        }
        cp_commit();

        const uint32_t sA = sb + (cc % 3)*STAGE;
        const uint32_t sB = sA + 32768;
        const int rA = wm*32 + (lane & 15);
        const int rB = wn*64 + (lane & 15);
#pragma unroll
        for (int ks = 0; ks < 4; ks++){
            const uint32_t choff = (uint32_t)(((ks*2 + (lane>>4)) ^ (lane&7)) << 4);
            uint32_t a[2][4], b[4][4];
#pragma unroll
            for (int mi = 0; mi < 2; mi++)
                ldmx4(a[mi], sA + (rA + mi*16)*128 + choff);
#pragma unroll
            for (int ni = 0; ni < 4; ni++)
                ldmx4(b[ni], sB + (rB + ni*16)*128 + choff);
#pragma unroll
            for (int mi = 0; mi < 2; mi++)
#pragma unroll
                for (int nj = 0; nj < 8; nj++)
                    mma_bf16(c[mi][nj], a[mi], b[nj>>1][nj&1], b[nj>>1][2+(nj&1)]);
        }
    }

    // ---- epilogue: mask, bias, relu, store NHWC ----
    const int gm0 = blockIdx.y*256 + wm*32;
    const int oc0 = blockIdx.x*128 + wn*64;
#pragma unroll
    for (int mi = 0; mi < 2; mi++){
#pragma unroll
        for (int half = 0; half < 2; half++){
            int n = gm0 + mi*16 + half*8 + (lane >> 2);
            if (n >= Nreal) continue;
            int mk = 1;
            if (mask){ int p = n % P; mk = mask[p]; }
            float* orow = Out + (size_t)n * OC;
#pragma unroll
            for (int nj = 0; nj < 8; nj++){
                int oc = oc0 + nj*8 + (lane & 3)*2;
                float v0 = (mk ? c[mi][nj][half*2+0] : 0.f) + __ldg(&bias[oc < OC ? oc : 0]);
                float v1 = (mk ? c[mi][nj][half*2+1] : 0.f) + __ldg(&bias[(oc+1) < OC ? (oc+1) : 0]);
                if (relu){ v0 = fmaxf(v0, 0.f); v1 = fmaxf(v1, 0.f); }
                if (oc + 1 < OC){
                    float2 v = {v0, v1};
                    *(float2*)(orow + oc) = v;
                } else if (oc < OC){
                    orow[oc] = v0;
                }
            }
        }
    }
}

// ======================= SIMT GEMM (layer 4 only) =======================
#define BN 64
#define BK 16
#define TN 4
template <int BMp, int TMp>
__global__ __launch_bounds__(256)
void k_gemm(const float* __restrict__ In, const float* __restrict__ Wt,
            const float* __restrict__ bias,
            const int* __restrict__ mask,
            float* __restrict__ Out,
            int IH, int IW, int IC, int OC,
            int OW, int P, int stride, int Ktot,
            int relu, int out_nchw)
{
    __shared__ float As[BK][BN + 1];
    __shared__ float Ws[BK][BMp];
    __shared__ int   s_base[BN];

    const int tid = threadIdx.x;
    const int n0  = blockIdx.x * BN;
    const int m0  = blockIdx.y * BMp;

    if (tid < BN) {
        int n  = n0 + tid;
        int b  = n / P;
        int p  = n - b * P;
        int oy = p / OW;
        int ox = p - oy * OW;
        s_base[tid] = ((b * IH + oy*stride) * IW + ox*stride) * IC;
    }
    __syncthreads();

    const int tx = tid & 15;
    const int ty = tid >> 4;

    constexpr int KSTEP = 256 / BMp;
    const int w_mm  = tid % BMp;
    const int w_kk0 = tid / BMp;
    const int a_kk  = tid & (BK - 1);
    const int a_nn0 = tid >> 4;

    float acc[TMp][TN];
#pragma unroll
    for (int i = 0; i < TMp; i++)
#pragma unroll
        for (int j = 0; j < TN; j++) acc[i][j] = 0.f;

    for (int k0 = 0; k0 < Ktot; k0 += BK) {
#pragma unroll
        for (int r = 0; r < BK / KSTEP; r++) {
            int kk = w_kk0 + r * KSTEP;
            int k  = k0 + kk;
            int m  = m0 + w_mm;
            Ws[kk][w_mm] = (k < Ktot && m < OC) ? Wt[k * OC + m] : 0.f;
        }
        {
            int  k   = k0 + a_kk;
            bool ok  = (k < Ktot);
            int  off = 0;
            if (ok) {
                int c   = k % IC;
                int tap = k / IC;
                int ky  = tap / 3, kx = tap - ky * 3;
                off = (ky * IW + kx) * IC + c;
            }
#pragma unroll
            for (int r = 0; r < 4; r++) {
                int nn = a_nn0 + 16 * r;
                As[a_kk][nn] = ok ? In[s_base[nn] + off] : 0.f;
            }
        }
        __syncthreads();

#pragma unroll
        for (int kk = 0; kk < BK; kk++) {
            float ra[TN], rb[TMp];
#pragma unroll
            for (int j = 0; j < TN; j++)  ra[j] = As[kk][tx * TN + j];
#pragma unroll
            for (int i = 0; i < TMp; i++) rb[i] = Ws[kk][ty * TMp + i];
#pragma unroll
            for (int i = 0; i < TMp; i++)
#pragma unroll
                for (int j = 0; j < TN; j++)
                    acc[i][j] = fmaf(rb[i], ra[j], acc[i][j]);
        }
        __syncthreads();
    }

#pragma unroll
    for (int j = 0; j < TN; j++) {
        int n = n0 + tx * TN + j;
        int b = n / P;
        int p = n - b * P;
        int mk = mask ? mask[p] : 1;
#pragma unroll
        for (int i = 0; i < TMp; i++) {
            int m = m0 + ty * TMp + i;
            if (m < OC) {
                float v = mk ? acc[i][j] : 0.f;
                v += __ldg(&bias[m]);
                if (relu) v = fmaxf(v, 0.f);
                if (out_nchw)
                    Out[(b * OC + m) * P + p] = v;
                else
                    Out[n * OC + m] = v;
            }
        }
    }
}

// ======================= launch =======================
extern "C" void kernel_launch(void* const* d_in, const int* in_sizes, int n_in,
                              void* d_out, int out_size) {
    const float* x     = (const float*)d_in[0];
    const float* w1    = (const float*)d_in[1];
    const float* b1    = (const float*)d_in[2];
    const float* w2    = (const float*)d_in[3];
    const float* b2    = (const float*)d_in[4];
    const float* w3    = (const float*)d_in[5];
    const float* b3    = (const float*)d_in[6];
    const float* w4    = (const float*)d_in[7];
    const float* b4    = (const float*)d_in[8];
    const int*   selh1 = (const int*)d_in[9];
    const int*   selw1 = (const int*)d_in[10];
    const int*   mask1 = (const int*)d_in[11];
    const int*   selh2 = (const int*)d_in[12];
    const int*   selw2 = (const int*)d_in[13];
    const int*   mask2 = (const int*)d_in[14];
    const int*   selh3 = (const int*)d_in[15];
    const int*   selw3 = (const int*)d_in[16];
    const int*   mask3 = (const int*)d_in[17];

    float *pX, *pO1, *pO2, *pO3, *pW4;
    __nv_bfloat16 *pA1, *pA2, *pA3, *pB1, *pB2, *pB3;
    cudaGetSymbolAddress((void**)&pX,  g_X);
    cudaGetSymbolAddress((void**)&pO1, g_O1);
    cudaGetSymbolAddress((void**)&pO2, g_O2);
    cudaGetSymbolAddress((void**)&pO3, g_O3);
    cudaGetSymbolAddress((void**)&pW4, g_W4t);
    cudaGetSymbolAddress((void**)&pA1, g_A1);
    cudaGetSymbolAddress((void**)&pA2, g_A2);
    cudaGetSymbolAddress((void**)&pA3, g_A3);
    cudaGetSymbolAddress((void**)&pB1, g_B1);
    cudaGetSymbolAddress((void**)&pB2, g_B2);
    cudaGetSymbolAddress((void**)&pB3, g_B3);

    cudaFuncSetAttribute(k_hmma, cudaFuncAttributeMaxDynamicSharedMemorySize, SMEM_HM);

    // x -> NHWC
    {
        int tot = 64 * 3 * 132 * 132;
        k_nchw2nhwc<<<(tot + 255) / 256, 256>>>(x, pX, 64, 3, 132, 132);
    }

    // ---- layer 1: 132x132x3 -> 65x65x200, K=27, PK=64 ----
    k_gather1<<<(270592 + 255) / 256, 256>>>(pX, pA1, selh1, selw1);
    {
        long wt = (long)256 * 192;
        k_wsplit<<<(unsigned)((wt + 255) / 256), 256>>>(w1, pB1, 200, 3, 27, 64, 256);
    }
    k_hmma<<<dim3(2, 1057), 512, SMEM_HM>>>(pA1, pB1, b1, mask1, pO1,
                                            64, 1, 200, 4225, 270400, 1);

    // ---- layer 2: 65x65x200 -> 31x31x400, K=1800, PK=1856 ----
    {
        long tot = (long)61696 * (1856/8);
        k_gather<<<(unsigned)((tot + 255) / 256), 256>>>(pO1, pA2, selh2, selw2,
            65, 65, 200, 31, 961, 2, 1800, 1856, 61504, 61696);
        long wt = (long)512 * 5568;
        k_wsplit<<<(unsigned)((wt + 255) / 256), 256>>>(w2, pB2, 400, 200, 1800, 1856, 512);
        k_hmma<<<dim3(4, 241), 512, SMEM_HM>>>(pA2, pB2, b2, mask2, pO2,
                                               1856, 29, 400, 961, 61504, 1);
    }

    // ---- layer 3: 31x31x400 -> 15x15x800, K=3600, PK=3648 ----
    {
        long tot = (long)14592 * (3648/8);
        k_gather<<<(unsigned)((tot + 255) / 256), 256>>>(pO2, pA3, selh3, selw3,
            31, 31, 400, 15, 225, 2, 3600, 3648, 14400, 14592);
        long wt = (long)896 * 10944;
        k_wsplit<<<(unsigned)((wt + 255) / 256), 256>>>(w3, pB3, 800, 400, 3600, 3648, 896);
        k_hmma<<<dim3(7, 57), 512, SMEM_HM>>>(pA3, pB3, b3, mask3, pO3,
                                              3648, 57, 800, 225, 14400, 1);
    }

    // ---- layer 4: dense 3x3 conv, SIMT fp32, NCHW output ----
    k_wt<<<(10 * 7200 + 255) / 256, 256>>>(w4, pW4, 10, 800);
    k_gemm<64, 4><<<dim3(169, 1), 256>>>(pO3, pW4, b4, nullptr,
                                         (float*)d_out,
                                         15, 15, 800, 10, 13, 13 * 13, 1, 7200, 0, 1);
}

// round 5
// speedup vs baseline: 1.0932x; 1.0932x over previous
#include <cuda_runtime.h>
#include <cuda_bf16.h>
#include <cstdint>

#define DINLINE __device__ __forceinline__

// ======================= scratch (device globals) =======================
__device__ __align__(16) float g_X [64*132*132*3];
__device__ __align__(16) float g_O1[64*65*65*200];
__device__ __align__(16) float g_O2[64*31*31*400];
__device__ __align__(16) float g_O3[64*15*15*800];
__device__ float g_W4t[7200*10];

// A: [Npad][2*PK]  (Ah | Al),  B: [OCpad][3*PK]  (Wh | Wl | Wh)
__device__ __align__(16) __nv_bfloat16 g_A1[(size_t)270592*128];
__device__ __align__(16) __nv_bfloat16 g_A2[(size_t)61696*3712];
__device__ __align__(16) __nv_bfloat16 g_A3[(size_t)14592*7296];
__device__ __align__(16) __nv_bfloat16 g_B1[(size_t)256*192];
__device__ __align__(16) __nv_bfloat16 g_B2[(size_t)512*5568];
__device__ __align__(16) __nv_bfloat16 g_B3[(size_t)896*10944];

// ======================= helpers =======================
DINLINE uint32_t smem_u32(const void* p){
    uint32_t a;
    asm("{ .reg .u64 t; cvta.to.shared.u64 t, %1; cvt.u32.u64 %0, t; }" : "=r"(a) : "l"(p));
    return a;
}
DINLINE void cp16(uint32_t dst, const void* src){
    asm volatile("cp.async.cg.shared.global [%0], [%1], 16;" :: "r"(dst), "l"(src));
}
DINLINE void cp_commit(){ asm volatile("cp.async.commit_group;" ::: "memory"); }
DINLINE void cp_wait1(){ asm volatile("cp.async.wait_group 1;" ::: "memory"); }

DINLINE void ldmx4(uint32_t r[4], uint32_t addr){
    asm volatile("ldmatrix.sync.aligned.m8n8.x4.shared.b16 {%0,%1,%2,%3}, [%4];"
        : "=r"(r[0]), "=r"(r[1]), "=r"(r[2]), "=r"(r[3]) : "r"(addr));
}
DINLINE void mma_bf16(float c[4], const uint32_t a[4], uint32_t b0, uint32_t b1){
    asm volatile("mma.sync.aligned.m16n8k16.row.col.f32.bf16.bf16.f32 "
        "{%0,%1,%2,%3}, {%4,%5,%6,%7}, {%8,%9}, {%0,%1,%2,%3};"
        : "+f"(c[0]), "+f"(c[1]), "+f"(c[2]), "+f"(c[3])
        : "r"(a[0]), "r"(a[1]), "r"(a[2]), "r"(a[3]), "r"(b0), "r"(b1));
}

// ======================= layout transforms =======================
__global__ void k_nchw2nhwc(const float* __restrict__ in, float* __restrict__ out,
                            int B, int C, int H, int W) {
    int idx = blockIdx.x * blockDim.x + threadIdx.x;
    if (idx >= B * C * H * W) return;
    int c = idx % C;
    int t = idx / C;
    int x = t % W; t /= W;
    int y = t % H; t /= H;
    out[idx] = in[((t * C + c) * H + y) * W + x];
}

__global__ void k_wt(const float* __restrict__ w, float* __restrict__ wt, int OC, int IC) {
    int idx = blockIdx.x * blockDim.x + threadIdx.x;
    if (idx >= OC * IC * 9) return;
    int oc  = idx % OC;
    int k   = idx / OC;
    int ic  = k % IC;
    int tap = k / IC;
    wt[idx] = w[(oc * IC + ic) * 9 + tap];
}

// W[oc][ic][3][3] -> B[ocpad][3*PK] bf16 blocks (Wh | Wl | Wh)
__global__ void k_wsplit(const float* __restrict__ W, __nv_bfloat16* __restrict__ Bw,
                         int OC, int IC, int Klayer, int PK, int OCpad)
{
    long idx = (long)blockIdx.x*blockDim.x + threadIdx.x;
    long total = (long)OCpad * 3 * PK;
    if (idx >= total) return;
    int ldb = 3 * PK;
    int oc = (int)(idx / ldb);
    int k2 = (int)(idx - (long)oc*ldb);
    int blk = k2 / PK, kk = k2 - blk*PK;
    __nv_bfloat16 out = __float2bfloat16(0.f);
    if (oc < OC && kk < Klayer){
        int tap = kk/IC, c = kk - tap*IC;
        float x = W[((size_t)oc*IC + c)*9 + tap];
        __nv_bfloat16 h = __float2bfloat16(x);
        out = (blk == 1) ? __float2bfloat16(x - __bfloat162float(h)) : h;
    }
    Bw[idx] = out;
}

// layers 2/3 gather: A[n][2*PK] = (Ah | Al). IC % 8 == 0.
__global__ void k_gather(const float* __restrict__ In, __nv_bfloat16* __restrict__ A,
                         const int* __restrict__ selh, const int* __restrict__ selw,
                         int IH, int IW, int IC, int OW, int P, int stride,
                         int Klayer, int PK, int Nreal, int Npad)
{
    int vecs = PK >> 3;
    long idx = (long)blockIdx.x*blockDim.x + threadIdx.x;
    if (idx >= (long)Npad * vecs) return;
    int n = (int)(idx / vecs);
    int v = (int)(idx - (long)n*vecs);
    int kk = v << 3;
    __nv_bfloat16 h[8], l[8];
    if (n < Nreal && kk < Klayer){
        int b = n / P, p = n - b*P;
        int oy = p / OW, ox = p - oy*OW;
        int ph = oy*stride + selh[p], pw = ox*stride + selw[p];
        int tap = kk / IC, c = kk - tap*IC;
        int ky = tap/3, kx = tap - ky*3;
        const float* src = In + ((size_t)((b*IH+ph+ky)*IW) + (pw+kx))*IC + c;
        float x[8];
        *(float4*)&x[0] = *(const float4*)src;
        *(float4*)&x[4] = *(const float4*)(src+4);
#pragma unroll
        for (int i=0;i<8;i++){
            __nv_bfloat16 hh = __float2bfloat16(x[i]);
            h[i] = hh;
            l[i] = __float2bfloat16(x[i] - __bfloat162float(hh));
        }
    } else {
#pragma unroll
        for (int i=0;i<8;i++){ h[i]=__float2bfloat16(0.f); l[i]=h[i]; }
    }
    __nv_bfloat16* row = A + (size_t)n * (2*PK);
    *(uint4*)(row + kk)      = *(uint4*)h;
    *(uint4*)(row + PK + kk) = *(uint4*)l;
}

// layer 1: IC=3, K=27, PK=64; A row = 128 cols (Ah|Al)
__global__ void k_gather1(const float* __restrict__ X, __nv_bfloat16* __restrict__ A,
                          const int* __restrict__ selh, const int* __restrict__ selw)
{
    int n = blockIdx.x*blockDim.x + threadIdx.x;
    if (n >= 270592) return;
    __nv_bfloat16 row[128];
#pragma unroll
    for (int i=0;i<128;i++) row[i] = __float2bfloat16(0.f);
    if (n < 270400){
        int b = n / 4225, p = n - b*4225;
        int oy = p/65, ox = p - oy*65;
        int ph = oy*2 + selh[p], pw = ox*2 + selw[p];
        const float* base = X + ((size_t)(b*132+ph)*132 + pw)*3;
#pragma unroll
        for (int ky=0;ky<3;ky++){
#pragma unroll
            for (int t=0;t<9;t++){
                float x = base[ky*396 + t];
                int k = ky*9 + t;
                __nv_bfloat16 h = __float2bfloat16(x);
                row[k]      = h;
                row[64 + k] = __float2bfloat16(x - __bfloat162float(h));
            }
        }
    }
    uint4* dst = (uint4*)(A + (size_t)n*128);
    uint4* s = (uint4*)row;
#pragma unroll
    for (int i=0;i<16;i++) dst[i] = s[i];
}

// ======================= HMMA GEMM =======================
// CTA tile 128(n) x 128(oc), BK=64 bf16, 256 threads (8 warps, 4x2), 2 CTAs/SM.
// 3-stage ring of 32KB; ONE barrier per chunk:
//   wait_group(1) -> syncthreads -> prefetch(cc+2) -> commit -> compute(cc)
static constexpr int STAGE = 32768;
static constexpr int SMEM_HM = 3 * STAGE;

__global__ __launch_bounds__(256, 2)
void k_hmma(const __nv_bfloat16* __restrict__ A, const __nv_bfloat16* __restrict__ B,
            const float* __restrict__ bias, const int* __restrict__ mask,
            float* __restrict__ Out,
            int PK, int PKc, int OC, int P, int Nreal, int relu)
{
    extern __shared__ char smem[];
    const uint32_t sb = smem_u32(smem);
    const int tid = threadIdx.x, lane = tid & 31, warp = tid >> 5;
    const int wm = warp >> 1, wn = warp & 1;   // 4 x 2 warp grid; warp tile 32 x 64

    const long ldA = 2L*PK, ldB = 3L*PK;
    // per-thread load geometry (hoisted): 1024 chunks = 128 rows x 8, 4 iters of 256
    const int l_row = tid >> 3, l_ch = tid & 7;
    const uint32_t l_soff = (uint32_t)(l_row*128 + ((l_ch ^ (l_row&7))<<4)); // +i*(32 rows*128)
    const __nv_bfloat16* Ag = A + (size_t)(blockIdx.y*128 + l_row) * ldA + l_ch*8;
    const __nv_bfloat16* Bg = B + (size_t)(blockIdx.x*128 + l_row) * ldB + l_ch*8;
    const long ldA32 = 32*ldA, ldB32 = 32*ldB;
    const int NC = 3 * PKc;

    float c[2][8][4];
#pragma unroll
    for (int i=0;i<2;i++)
#pragma unroll
        for (int j=0;j<8;j++)
#pragma unroll
            for (int k=0;k<4;k++) c[i][j][k] = 0.f;

    // prologue: chunks 0,1
    {
        uint32_t sA = sb, sB = sb + 16384;
#pragma unroll
        for (int i=0;i<4;i++) cp16(sA + l_soff + i*4096, Ag + i*ldA32);
#pragma unroll
        for (int i=0;i<4;i++) cp16(sB + l_soff + i*4096, Bg + i*ldB32);
        cp_commit();
        if (NC > 1){
            int blk = 1 / PKc, ci = 1 - blk*PKc;
            int ac = (blk==2 ? PK : 0) + ci*64;
            sA = sb + STAGE; sB = sA + 16384;
#pragma unroll
            for (int i=0;i<4;i++) cp16(sA + l_soff + i*4096, Ag + ac + i*ldA32);
#pragma unroll
            for (int i=0;i<4;i++) cp16(sB + l_soff + i*4096, Bg + 64 + i*ldB32);
        }
        cp_commit();
    }

#pragma unroll 1
    for (int cc = 0; cc < NC; cc++){
        cp_wait1();                 // chunk cc resident
        __syncthreads();            // all warps done computing chunk cc-1
        if (cc + 2 < NC){           // prefetch chunk cc+2 into stage (cc-1)%3
            int c2 = cc + 2;
            int blk = c2 / PKc, ci = c2 - blk*PKc;
            int ac = (blk==2 ? PK : 0) + ci*64;
            uint32_t sA = sb + (c2 % 3)*STAGE, sB = sA + 16384;
#pragma unroll
            for (int i=0;i<4;i++) cp16(sA + l_soff + i*4096, Ag + ac + i*ldA32);
#pragma unroll
            for (int i=0;i<4;i++) cp16(sB + l_soff + i*4096, Bg + c2*64 + i*ldB32);
        }
        cp_commit();

        const uint32_t sA = sb + (cc % 3)*STAGE;
        const uint32_t sB = sA + 16384;
        const int rA = wm*32 + (lane & 15);
        const int rB = wn*64 + (lane & 15);
#pragma unroll
        for (int ks = 0; ks < 4; ks++){
            const uint32_t choff = (uint32_t)(((ks*2 + (lane>>4)) ^ (lane&7)) << 4);
            uint32_t a[2][4], b[4][4];
#pragma unroll
            for (int mi = 0; mi < 2; mi++)
                ldmx4(a[mi], sA + (rA + mi*16)*128 + choff);
#pragma unroll
            for (int ni = 0; ni < 4; ni++)
                ldmx4(b[ni], sB + (rB + ni*16)*128 + choff);
#pragma unroll
            for (int mi = 0; mi < 2; mi++)
#pragma unroll
                for (int nj = 0; nj < 8; nj++)
                    mma_bf16(c[mi][nj], a[mi], b[nj>>1][nj&1], b[nj>>1][2+(nj&1)]);
        }
    }

    // ---- epilogue: mask, bias, relu, store NHWC ----
    const int gm0 = blockIdx.y*128 + wm*32;
    const int oc0 = blockIdx.x*128 + wn*64;
#pragma unroll
    for (int mi = 0; mi < 2; mi++){
#pragma unroll
        for (int half = 0; half < 2; half++){
            int n = gm0 + mi*16 + half*8 + (lane >> 2);
            if (n >= Nreal) continue;
            int mk = 1;
            if (mask){ int p = n % P; mk = mask[p]; }
            float* orow = Out + (size_t)n * OC;
#pragma unroll
            for (int nj = 0; nj < 8; nj++){
                int oc = oc0 + nj*8 + (lane & 3)*2;
                float v0 = (mk ? c[mi][nj][half*2+0] : 0.f) + __ldg(&bias[oc < OC ? oc : 0]);
                float v1 = (mk ? c[mi][nj][half*2+1] : 0.f) + __ldg(&bias[(oc+1) < OC ? (oc+1) : 0]);
                if (relu){ v0 = fmaxf(v0, 0.f); v1 = fmaxf(v1, 0.f); }
                if (oc + 1 < OC){
                    float2 v = {v0, v1};
                    *(float2*)(orow + oc) = v;
                } else if (oc < OC){
                    orow[oc] = v0;
                }
            }
        }
    }
}

// ======================= SIMT GEMM (layer 4 only) =======================
#define BN 64
#define BK 16
#define TN 4
template <int BMp, int TMp>
__global__ __launch_bounds__(256)
void k_gemm(const float* __restrict__ In, const float* __restrict__ Wt,
            const float* __restrict__ bias,
            const int* __restrict__ mask,
            float* __restrict__ Out,
            int IH, int IW, int IC, int OC,
            int OW, int P, int stride, int Ktot,
            int relu, int out_nchw)
{
    __shared__ float As[BK][BN + 1];
    __shared__ float Ws[BK][BMp];
    __shared__ int   s_base[BN];

    const int tid = threadIdx.x;
    const int n0  = blockIdx.x * BN;
    const int m0  = blockIdx.y * BMp;

    if (tid < BN) {
        int n  = n0 + tid;
        int b  = n / P;
        int p  = n - b * P;
        int oy = p / OW;
        int ox = p - oy * OW;
        s_base[tid] = ((b * IH + oy*stride) * IW + ox*stride) * IC;
    }
    __syncthreads();

    const int tx = tid & 15;
    const int ty = tid >> 4;

    constexpr int KSTEP = 256 / BMp;
    const int w_mm  = tid % BMp;
    const int w_kk0 = tid / BMp;
    const int a_kk  = tid & (BK - 1);
    const int a_nn0 = tid >> 4;

    float acc[TMp][TN];
#pragma unroll
    for (int i = 0; i < TMp; i++)
#pragma unroll
        for (int j = 0; j < TN; j++) acc[i][j] = 0.f;

    for (int k0 = 0; k0 < Ktot; k0 += BK) {
#pragma unroll
        for (int r = 0; r < BK / KSTEP; r++) {
            int kk = w_kk0 + r * KSTEP;
            int k  = k0 + kk;
            int m  = m0 + w_mm;
            Ws[kk][w_mm] = (k < Ktot && m < OC) ? Wt[k * OC + m] : 0.f;
        }
        {
            int  k   = k0 + a_kk;
            bool ok  = (k < Ktot);
            int  off = 0;
            if (ok) {
                int c   = k % IC;
                int tap = k / IC;
                int ky  = tap / 3, kx = tap - ky * 3;
                off = (ky * IW + kx) * IC + c;
            }
#pragma unroll
            for (int r = 0; r < 4; r++) {
                int nn = a_nn0 + 16 * r;
                As[a_kk][nn] = ok ? In[s_base[nn] + off] : 0.f;
            }
        }
        __syncthreads();

#pragma unroll
        for (int kk = 0; kk < BK; kk++) {
            float ra[TN], rb[TMp];
#pragma unroll
            for (int j = 0; j < TN; j++)  ra[j] = As[kk][tx * TN + j];
#pragma unroll
            for (int i = 0; i < TMp; i++) rb[i] = Ws[kk][ty * TMp + i];
#pragma unroll
            for (int i = 0; i < TMp; i++)
#pragma unroll
                for (int j = 0; j < TN; j++)
                    acc[i][j] = fmaf(rb[i], ra[j], acc[i][j]);
        }
        __syncthreads();
    }

#pragma unroll
    for (int j = 0; j < TN; j++) {
        int n = n0 + tx * TN + j;
        int b = n / P;
        int p = n - b * P;
        int mk = mask ? mask[p] : 1;
#pragma unroll
        for (int i = 0; i < TMp; i++) {
            int m = m0 + ty * TMp + i;
            if (m < OC) {
                float v = mk ? acc[i][j] : 0.f;
                v += __ldg(&bias[m]);
                if (relu) v = fmaxf(v, 0.f);
                if (out_nchw)
                    Out[(b * OC + m) * P + p] = v;
                else
                    Out[n * OC + m] = v;
            }
        }
    }
}

// ======================= launch =======================
extern "C" void kernel_launch(void* const* d_in, const int* in_sizes, int n_in,
                              void* d_out, int out_size) {
    const float* x     = (const float*)d_in[0];
    const float* w1    = (const float*)d_in[1];
    const float* b1    = (const float*)d_in[2];
    const float* w2    = (const float*)d_in[3];
    const float* b2    = (const float*)d_in[4];
    const float* w3    = (const float*)d_in[5];
    const float* b3    = (const float*)d_in[6];
    const float* w4    = (const float*)d_in[7];
    const float* b4    = (const float*)d_in[8];
    const int*   selh1 = (const int*)d_in[9];
    const int*   selw1 = (const int*)d_in[10];
    const int*   mask1 = (const int*)d_in[11];
    const int*   selh2 = (const int*)d_in[12];
    const int*   selw2 = (const int*)d_in[13];
    const int*   mask2 = (const int*)d_in[14];
    const int*   selh3 = (const int*)d_in[15];
    const int*   selw3 = (const int*)d_in[16];
    const int*   mask3 = (const int*)d_in[17];

    float *pX, *pO1, *pO2, *pO3, *pW4;
    __nv_bfloat16 *pA1, *pA2, *pA3, *pB1, *pB2, *pB3;
    cudaGetSymbolAddress((void**)&pX,  g_X);
    cudaGetSymbolAddress((void**)&pO1, g_O1);
    cudaGetSymbolAddress((void**)&pO2, g_O2);
    cudaGetSymbolAddress((void**)&pO3, g_O3);
    cudaGetSymbolAddress((void**)&pW4, g_W4t);
    cudaGetSymbolAddress((void**)&pA1, g_A1);
    cudaGetSymbolAddress((void**)&pA2, g_A2);
    cudaGetSymbolAddress((void**)&pA3, g_A3);
    cudaGetSymbolAddress((void**)&pB1, g_B1);
    cudaGetSymbolAddress((void**)&pB2, g_B2);
    cudaGetSymbolAddress((void**)&pB3, g_B3);

    cudaFuncSetAttribute(k_hmma, cudaFuncAttributeMaxDynamicSharedMemorySize, SMEM_HM);

    // x -> NHWC
    {
        int tot = 64 * 3 * 132 * 132;
        k_nchw2nhwc<<<(tot + 255) / 256, 256>>>(x, pX, 64, 3, 132, 132);
    }

    // ---- layer 1: 132x132x3 -> 65x65x200, K=27, PK=64 ----
    k_gather1<<<(270592 + 255) / 256, 256>>>(pX, pA1, selh1, selw1);
    {
        long wt = (long)256 * 192;
        k_wsplit<<<(unsigned)((wt + 255) / 256), 256>>>(w1, pB1, 200, 3, 27, 64, 256);
    }
    k_hmma<<<dim3(2, 2114), 256, SMEM_HM>>>(pA1, pB1, b1, mask1, pO1,
                                            64, 1, 200, 4225, 270400, 1);

    // ---- layer 2: 65x65x200 -> 31x31x400, K=1800, PK=1856 ----
    {
        long tot = (long)61696 * (1856/8);
        k_gather<<<(unsigned)((tot + 255) / 256), 256>>>(pO1, pA2, selh2, selw2,
            65, 65, 200, 31, 961, 2, 1800, 1856, 61504, 61696);
        long wt = (long)512 * 5568;
        k_wsplit<<<(unsigned)((wt + 255) / 256), 256>>>(w2, pB2, 400, 200, 1800, 1856, 512);
        k_hmma<<<dim3(4, 482), 256, SMEM_HM>>>(pA2, pB2, b2, mask2, pO2,
                                               1856, 29, 400, 961, 61504, 1);
    }

    // ---- layer 3: 31x31x400 -> 15x15x800, K=3600, PK=3648 ----
    {
        long tot = (long)14592 * (3648/8);
        k_gather<<<(unsigned)((tot + 255) / 256), 256>>>(pO2, pA3, selh3, selw3,
            31, 31, 400, 15, 225, 2, 3600, 3648, 14400, 14592);
        long wt = (long)896 * 10944;
        k_wsplit<<<(unsigned)((wt + 255) / 256), 256>>>(w3, pB3, 800, 400, 3600, 3648, 896);
        k_hmma<<<dim3(7, 114), 256, SMEM_HM>>>(pA3, pB3, b3, mask3, pO3,
                                               3648, 57, 800, 225, 14400, 1);
    }

    // ---- layer 4: dense 3x3 conv, SIMT fp32, NCHW output ----
    k_wt<<<(10 * 7200 + 255) / 256, 256>>>(w4, pW4, 10, 800);
    k_gemm<64, 4><<<dim3(169, 1), 256>>>(pO3, pW4, b4, nullptr,
                                         (float*)d_out,
                                         15, 15, 800, 10, 13, 13 * 13, 1, 7200, 0, 1);
}

// round 6
// speedup vs baseline: 1.8099x; 1.6555x over previous
#include <cuda_runtime.h>
#include <cuda_bf16.h>
#include <cuda_fp16.h>
#include <cstdint>

#define DINLINE __device__ __forceinline__

// ======================= scratch (device globals) =======================
__device__ __align__(16) float g_X [64*132*132*3];
__device__ __align__(16) float g_O1[64*65*65*200];
__device__ __align__(16) float g_O2[64*31*31*400];
__device__ __align__(16) float g_O3[64*15*15*800];
__device__ float g_W4t[7200*10];

// L1 (bf16 packed 3-term): A1[Npad=270592][128], B1[256][128]
// L2/L3 (fp16 single): A[Npad][Kpad], B[OCpad][Kpad]
__device__ __align__(16) __nv_bfloat16 g_A1[(size_t)270592*128];
__device__ __align__(16) __half        g_A2[(size_t)61696*1856];
__device__ __align__(16) __half        g_A3[(size_t)14592*3648];
__device__ __align__(16) __nv_bfloat16 g_B1[(size_t)256*128];
__device__ __align__(16) __half        g_B2[(size_t)512*1856];
__device__ __align__(16) __half        g_B3[(size_t)896*3648];

// ======================= helpers =======================
DINLINE uint32_t smem_u32(const void* p){
    uint32_t a;
    asm("{ .reg .u64 t; cvta.to.shared.u64 t, %1; cvt.u32.u64 %0, t; }" : "=r"(a) : "l"(p));
    return a;
}
DINLINE void cp16(uint32_t dst, const void* src){
    asm volatile("cp.async.cg.shared.global [%0], [%1], 16;" :: "r"(dst), "l"(src));
}
DINLINE void cp_commit(){ asm volatile("cp.async.commit_group;" ::: "memory"); }
DINLINE void cp_wait1(){ asm volatile("cp.async.wait_group 1;" ::: "memory"); }

DINLINE void ldmx4(uint32_t r[4], uint32_t addr){
    asm volatile("ldmatrix.sync.aligned.m8n8.x4.shared.b16 {%0,%1,%2,%3}, [%4];"
        : "=r"(r[0]), "=r"(r[1]), "=r"(r[2]), "=r"(r[3]) : "r"(addr));
}
DINLINE void mma_bf16(float c[4], const uint32_t a[4], uint32_t b0, uint32_t b1){
    asm volatile("mma.sync.aligned.m16n8k16.row.col.f32.bf16.bf16.f32 "
        "{%0,%1,%2,%3}, {%4,%5,%6,%7}, {%8,%9}, {%0,%1,%2,%3};"
        : "+f"(c[0]), "+f"(c[1]), "+f"(c[2]), "+f"(c[3])
        : "r"(a[0]), "r"(a[1]), "r"(a[2]), "r"(a[3]), "r"(b0), "r"(b1));
}
DINLINE void mma_fp16(float c[4], const uint32_t a[4], uint32_t b0, uint32_t b1){
    asm volatile("mma.sync.aligned.m16n8k16.row.col.f32.f16.f16.f32 "
        "{%0,%1,%2,%3}, {%4,%5,%6,%7}, {%8,%9}, {%0,%1,%2,%3};"
        : "+f"(c[0]), "+f"(c[1]), "+f"(c[2]), "+f"(c[3])
        : "r"(a[0]), "r"(a[1]), "r"(a[2]), "r"(a[3]), "r"(b0), "r"(b1));
}

// ======================= layout transforms =======================
__global__ void k_nchw2nhwc(const float* __restrict__ in, float* __restrict__ out,
                            int B, int C, int H, int W) {
    int idx = blockIdx.x * blockDim.x + threadIdx.x;
    if (idx >= B * C * H * W) return;
    int c = idx % C;
    int t = idx / C;
    int x = t % W; t /= W;
    int y = t % H; t /= H;
    out[idx] = in[((t * C + c) * H + y) * W + x];
}

__global__ void k_wt(const float* __restrict__ w, float* __restrict__ wt, int OC, int IC) {
    int idx = blockIdx.x * blockDim.x + threadIdx.x;
    if (idx >= OC * IC * 9) return;
    int oc  = idx % OC;
    int k   = idx / OC;
    int ic  = k % IC;
    int tap = k / IC;
    wt[idx] = w[(oc * IC + ic) * 9 + tap];
}

// ---- layer 1 weights (bf16 packed 3-term, Kpad=128) ----
// cols [0:27)=Wh, [27:54)=Wh (pairs with Al), [64:91)=Wl ; k = tap*3 + ic
__global__ void k_wsplit1(const float* __restrict__ W, __nv_bfloat16* __restrict__ Bw)
{
    int idx = blockIdx.x*blockDim.x + threadIdx.x;
    if (idx >= 256*128) return;
    int oc = idx >> 7, j = idx & 127;
    __nv_bfloat16 out = __float2bfloat16(0.f);
    if (oc < 200){
        int k = -1; bool lo = false;
        if (j < 27)              k = j;
        else if (j < 54)         k = j - 27;
        else if (j >= 64 && j < 91){ k = j - 64; lo = true; }
        if (k >= 0){
            int tap = k/3, c = k - tap*3;
            float x = W[((size_t)oc*3 + c)*9 + tap];
            __nv_bfloat16 h = __float2bfloat16(x);
            out = lo ? __float2bfloat16(x - __bfloat162float(h)) : h;
        }
    }
    Bw[idx] = out;
}

// ---- layers 2/3 weights: fp16 single, [OCpad][Kpad] ----
__global__ void k_wcvt(const float* __restrict__ W, __half* __restrict__ Bw,
                       int OC, int IC, int Klayer, int Kpad, int OCpad)
{
    long idx = (long)blockIdx.x*blockDim.x + threadIdx.x;
    if (idx >= (long)OCpad * Kpad) return;
    int oc = (int)(idx / Kpad);
    int kk = (int)(idx - (long)oc*Kpad);
    __half out = __float2half_rn(0.f);
    if (oc < OC && kk < Klayer){
        int tap = kk/IC, c = kk - tap*IC;
        out = __float2half_rn(W[((size_t)oc*IC + c)*9 + tap]);
    }
    Bw[idx] = out;
}

// ---- layers 2/3 gather: fp16 single, A[n][Kpad]. IC % 8 == 0. ----
__global__ void k_gather(const float* __restrict__ In, __half* __restrict__ A,
                         const int* __restrict__ selh, const int* __restrict__ selw,
                         int IH, int IW, int IC, int OW, int P, int stride,
                         int Klayer, int Kpad, int Nreal, int Npad)
{
    int vecs = Kpad >> 3;
    long idx = (long)blockIdx.x*blockDim.x + threadIdx.x;
    if (idx >= (long)Npad * vecs) return;
    int n = (int)(idx / vecs);
    int v = (int)(idx - (long)n*vecs);
    int kk = v << 3;
    __half h[8];
    if (n < Nreal && kk < Klayer){
        int b = n / P, p = n - b*P;
        int oy = p / OW, ox = p - oy*OW;
        int ph = oy*stride + selh[p], pw = ox*stride + selw[p];
        int tap = kk / IC, c = kk - tap*IC;
        int ky = tap/3, kx = tap - ky*3;
        const float* src = In + ((size_t)((b*IH+ph+ky)*IW) + (pw+kx))*IC + c;
        float x[8];
        *(float4*)&x[0] = *(const float4*)src;
        *(float4*)&x[4] = *(const float4*)(src+4);
#pragma unroll
        for (int i=0;i<8;i++) h[i] = __float2half_rn(x[i]);
    } else {
#pragma unroll
        for (int i=0;i<8;i++) h[i] = __float2half_rn(0.f);
    }
    *(uint4*)(A + (size_t)n*Kpad + kk) = *(uint4*)h;
}

// ---- layer 1 gather: bf16 packed 3-term, Kpad=128 ----
// cols [0:27)=Ah, [27:54)=Al, [64:91)=Ah
__global__ void k_gather1(const float* __restrict__ X, __nv_bfloat16* __restrict__ A,
                          const int* __restrict__ selh, const int* __restrict__ selw)
{
    int n = blockIdx.x*blockDim.x + threadIdx.x;
    if (n >= 270592) return;
    __nv_bfloat16 row[128];
#pragma unroll
    for (int i=0;i<128;i++) row[i] = __float2bfloat16(0.f);
    if (n < 270400){
        int b = n / 4225, p = n - b*4225;
        int oy = p/65, ox = p - oy*65;
        int ph = oy*2 + selh[p], pw = ox*2 + selw[p];
        const float* base = X + ((size_t)(b*132+ph)*132 + pw)*3;
#pragma unroll
        for (int ky=0;ky<3;ky++){
#pragma unroll
            for (int t=0;t<9;t++){
                float x = base[ky*396 + t];
                int k = ky*9 + t;
                __nv_bfloat16 h = __float2bfloat16(x);
                row[k]      = h;                                        // Ah (x Wh)
                row[27 + k] = __float2bfloat16(x - __bfloat162float(h)); // Al (x Wh)
                row[64 + k] = h;                                        // Ah (x Wl)
            }
        }
    }
    uint4* dst = (uint4*)(A + (size_t)n*128);
    uint4* s = (uint4*)row;
#pragma unroll
    for (int i=0;i<16;i++) dst[i] = s[i];
}

// ======================= HMMA GEMM (identity K schedule) =======================
// CTA tile 128(n) x 128(oc), BK=64, 256 threads (8 warps, 4x2), 2 CTAs/SM.
// 3-stage ring of 32KB; chunk cc reads cols [cc*64, cc*64+64) of both A and B.
static constexpr int STAGE = 32768;
static constexpr int SMEM_HM = 3 * STAGE;

template <bool BF16>
__global__ __launch_bounds__(256, 2)
void k_hmma(const uint16_t* __restrict__ A, const uint16_t* __restrict__ B,
            const float* __restrict__ bias, const int* __restrict__ mask,
            float* __restrict__ Out,
            int ldK, int NC, int OC, int P, int Nreal, int relu)
{
    extern __shared__ char smem[];
    const uint32_t sb = smem_u32(smem);
    const int tid = threadIdx.x, lane = tid & 31, warp = tid >> 5;
    const int wm = warp >> 1, wn = warp & 1;   // 4 x 2 warp grid; warp tile 32 x 64

    const long ld = (long)ldK;
    const int l_row = tid >> 3, l_ch = tid & 7;
    const uint32_t l_soff = (uint32_t)(l_row*128 + ((l_ch ^ (l_row&7))<<4));
    const uint16_t* Ag = A + (size_t)(blockIdx.y*128 + l_row) * ld + l_ch*8;
    const uint16_t* Bg = B + (size_t)(blockIdx.x*128 + l_row) * ld + l_ch*8;
    const long ld32 = 32*ld;

    float c[2][8][4];
#pragma unroll
    for (int i=0;i<2;i++)
#pragma unroll
        for (int j=0;j<8;j++)
#pragma unroll
            for (int k=0;k<4;k++) c[i][j][k] = 0.f;

    // prologue: chunks 0,1
    {
        uint32_t sA = sb, sB = sb + 16384;
#pragma unroll
        for (int i=0;i<4;i++) cp16(sA + l_soff + i*4096, Ag + i*ld32);
#pragma unroll
        for (int i=0;i<4;i++) cp16(sB + l_soff + i*4096, Bg + i*ld32);
        cp_commit();
        if (NC > 1){
            sA = sb + STAGE; sB = sA + 16384;
#pragma unroll
            for (int i=0;i<4;i++) cp16(sA + l_soff + i*4096, Ag + 64 + i*ld32);
#pragma unroll
            for (int i=0;i<4;i++) cp16(sB + l_soff + i*4096, Bg + 64 + i*ld32);
        }
        cp_commit();
    }

#pragma unroll 1
    for (int cc = 0; cc < NC; cc++){
        cp_wait1();
        __syncthreads();
        if (cc + 2 < NC){
            int c2 = cc + 2;
            uint32_t sA = sb + (c2 % 3)*STAGE, sB = sA + 16384;
#pragma unroll
            for (int i=0;i<4;i++) cp16(sA + l_soff + i*4096, Ag + c2*64 + i*ld32);
#pragma unroll
            for (int i=0;i<4;i++) cp16(sB + l_soff + i*4096, Bg + c2*64 + i*ld32);
        }
        cp_commit();

        const uint32_t sA = sb + (cc % 3)*STAGE;
        const uint32_t sB = sA + 16384;
        const int rA = wm*32 + (lane & 15);
        const int rB = wn*64 + (lane & 15);
#pragma unroll
        for (int ks = 0; ks < 4; ks++){
            const uint32_t choff = (uint32_t)(((ks*2 + (lane>>4)) ^ (lane&7)) << 4);
            uint32_t a[2][4], b[4][4];
#pragma unroll
            for (int mi = 0; mi < 2; mi++)
                ldmx4(a[mi], sA + (rA + mi*16)*128 + choff);
#pragma unroll
            for (int ni = 0; ni < 4; ni++)
                ldmx4(b[ni], sB + (rB + ni*16)*128 + choff);
#pragma unroll
            for (int mi = 0; mi < 2; mi++)
#pragma unroll
                for (int nj = 0; nj < 8; nj++){
                    if (BF16) mma_bf16(c[mi][nj], a[mi], b[nj>>1][nj&1], b[nj>>1][2+(nj&1)]);
                    else      mma_fp16(c[mi][nj], a[mi], b[nj>>1][nj&1], b[nj>>1][2+(nj&1)]);
                }
        }
    }

    // ---- epilogue: mask, bias, relu, store NHWC ----
    const int gm0 = blockIdx.y*128 + wm*32;
    const int oc0 = blockIdx.x*128 + wn*64;
#pragma unroll
    for (int mi = 0; mi < 2; mi++){
#pragma unroll
        for (int half = 0; half < 2; half++){
            int n = gm0 + mi*16 + half*8 + (lane >> 2);
            if (n >= Nreal) continue;
            int mk = 1;
            if (mask){ int p = n % P; mk = mask[p]; }
            float* orow = Out + (size_t)n * OC;
#pragma unroll
            for (int nj = 0; nj < 8; nj++){
                int oc = oc0 + nj*8 + (lane & 3)*2;
                float v0 = (mk ? c[mi][nj][half*2+0] : 0.f) + __ldg(&bias[oc < OC ? oc : 0]);
                float v1 = (mk ? c[mi][nj][half*2+1] : 0.f) + __ldg(&bias[(oc+1) < OC ? (oc+1) : 0]);
                if (relu){ v0 = fmaxf(v0, 0.f); v1 = fmaxf(v1, 0.f); }
                if (oc + 1 < OC){
                    float2 v = {v0, v1};
                    *(float2*)(orow + oc) = v;
                } else if (oc < OC){
                    orow[oc] = v0;
                }
            }
        }
    }
}

// ======================= SIMT GEMM (layer 4 only) =======================
#define BN 64
#define BK 16
#define TN 4
template <int BMp, int TMp>
__global__ __launch_bounds__(256)
void k_gemm(const float* __restrict__ In, const float* __restrict__ Wt,
            const float* __restrict__ bias,
            const int* __restrict__ mask,
            float* __restrict__ Out,
            int IH, int IW, int IC, int OC,
            int OW, int P, int stride, int Ktot,
            int relu, int out_nchw)
{
    __shared__ float As[BK][BN + 1];
    __shared__ float Ws[BK][BMp];
    __shared__ int   s_base[BN];

    const int tid = threadIdx.x;
    const int n0  = blockIdx.x * BN;
    const int m0  = blockIdx.y * BMp;

    if (tid < BN) {
        int n  = n0 + tid;
        int b  = n / P;
        int p  = n - b * P;
        int oy = p / OW;
        int ox = p - oy * OW;
        s_base[tid] = ((b * IH + oy*stride) * IW + ox*stride) * IC;
    }
    __syncthreads();

    const int tx = tid & 15;
    const int ty = tid >> 4;

    constexpr int KSTEP = 256 / BMp;
    const int w_mm  = tid % BMp;
    const int w_kk0 = tid / BMp;
    const int a_kk  = tid & (BK - 1);
    const int a_nn0 = tid >> 4;

    float acc[TMp][TN];
#pragma unroll
    for (int i = 0; i < TMp; i++)
#pragma unroll
        for (int j = 0; j < TN; j++) acc[i][j] = 0.f;

    for (int k0 = 0; k0 < Ktot; k0 += BK) {
#pragma unroll
        for (int r = 0; r < BK / KSTEP; r++) {
            int kk = w_kk0 + r * KSTEP;
            int k  = k0 + kk;
            int m  = m0 + w_mm;
            Ws[kk][w_mm] = (k < Ktot && m < OC) ? Wt[k * OC + m] : 0.f;
        }
        {
            int  k   = k0 + a_kk;
            bool ok  = (k < Ktot);
            int  off = 0;
            if (ok) {
                int c   = k % IC;
                int tap = k / IC;
                int ky  = tap / 3, kx = tap - ky * 3;
                off = (ky * IW + kx) * IC + c;
            }
#pragma unroll
            for (int r = 0; r < 4; r++) {
                int nn = a_nn0 + 16 * r;
                As[a_kk][nn] = ok ? In[s_base[nn] + off] : 0.f;
            }
        }
        __syncthreads();

#pragma unroll
        for (int kk = 0; kk < BK; kk++) {
            float ra[TN], rb[TMp];
#pragma unroll
            for (int j = 0; j < TN; j++)  ra[j] = As[kk][tx * TN + j];
#pragma unroll
            for (int i = 0; i < TMp; i++) rb[i] = Ws[kk][ty * TMp + i];
#pragma unroll
            for (int i = 0; i < TMp; i++)
#pragma unroll
                for (int j = 0; j < TN; j++)
                    acc[i][j] = fmaf(rb[i], ra[j], acc[i][j]);
        }
        __syncthreads();
    }

#pragma unroll
    for (int j = 0; j < TN; j++) {
        int n = n0 + tx * TN + j;
        int b = n / P;
        int p = n - b * P;
        int mk = mask ? mask[p] : 1;
#pragma unroll
        for (int i = 0; i < TMp; i++) {
            int m = m0 + ty * TMp + i;
            if (m < OC) {
                float v = mk ? acc[i][j] : 0.f;
                v += __ldg(&bias[m]);
                if (relu) v = fmaxf(v, 0.f);
                if (out_nchw)
                    Out[(b * OC + m) * P + p] = v;
                else
                    Out[n * OC + m] = v;
            }
        }
    }
}

// ======================= launch =======================
extern "C" void kernel_launch(void* const* d_in, const int* in_sizes, int n_in,
                              void* d_out, int out_size) {
    const float* x     = (const float*)d_in[0];
    const float* w1    = (const float*)d_in[1];
    const float* b1    = (const float*)d_in[2];
    const float* w2    = (const float*)d_in[3];
    const float* b2    = (const float*)d_in[4];
    const float* w3    = (const float*)d_in[5];
    const float* b3    = (const float*)d_in[6];
    const float* w4    = (const float*)d_in[7];
    const float* b4    = (const float*)d_in[8];
    const int*   selh1 = (const int*)d_in[9];
    const int*   selw1 = (const int*)d_in[10];
    const int*   mask1 = (const int*)d_in[11];
    const int*   selh2 = (const int*)d_in[12];
    const int*   selw2 = (const int*)d_in[13];
    const int*   mask2 = (const int*)d_in[14];
    const int*   selh3 = (const int*)d_in[15];
    const int*   selw3 = (const int*)d_in[16];
    const int*   mask3 = (const int*)d_in[17];

    float *pX, *pO1, *pO2, *pO3, *pW4;
    __nv_bfloat16 *pA1, *pB1;
    __half *pA2, *pA3, *pB2, *pB3;
    cudaGetSymbolAddress((void**)&pX,  g_X);
    cudaGetSymbolAddress((void**)&pO1, g_O1);
    cudaGetSymbolAddress((void**)&pO2, g_O2);
    cudaGetSymbolAddress((void**)&pO3, g_O3);
    cudaGetSymbolAddress((void**)&pW4, g_W4t);
    cudaGetSymbolAddress((void**)&pA1, g_A1);
    cudaGetSymbolAddress((void**)&pA2, g_A2);
    cudaGetSymbolAddress((void**)&pA3, g_A3);
    cudaGetSymbolAddress((void**)&pB1, g_B1);
    cudaGetSymbolAddress((void**)&pB2, g_B2);
    cudaGetSymbolAddress((void**)&pB3, g_B3);

    cudaFuncSetAttribute(k_hmma<true>,  cudaFuncAttributeMaxDynamicSharedMemorySize, SMEM_HM);
    cudaFuncSetAttribute(k_hmma<false>, cudaFuncAttributeMaxDynamicSharedMemorySize, SMEM_HM);

    // x -> NHWC
    {
        int tot = 64 * 3 * 132 * 132;
        k_nchw2nhwc<<<(tot + 255) / 256, 256>>>(x, pX, 64, 3, 132, 132);
    }

    // ---- layer 1: bf16 packed 3-term, Kpad=128, NC=2 ----
    k_gather1<<<(270592 + 255) / 256, 256>>>(pX, pA1, selh1, selw1);
    k_wsplit1<<<(256*128 + 255) / 256, 256>>>(w1, pB1);
    k_hmma<true><<<dim3(2, 2114), 256, SMEM_HM>>>(
        (const uint16_t*)pA1, (const uint16_t*)pB1, b1, mask1, pO1,
        128, 2, 200, 4225, 270400, 1);

    // ---- layer 2: fp16 single, K=1800, Kpad=1856, NC=29 ----
    {
        long tot = (long)61696 * (1856/8);
        k_gather<<<(unsigned)((tot + 255) / 256), 256>>>(pO1, pA2, selh2, selw2,
            65, 65, 200, 31, 961, 2, 1800, 1856, 61504, 61696);
        long wt = (long)512 * 1856;
        k_wcvt<<<(unsigned)((wt + 255) / 256), 256>>>(w2, pB2, 400, 200, 1800, 1856, 512);
        k_hmma<false><<<dim3(4, 482), 256, SMEM_HM>>>(
            (const uint16_t*)pA2, (const uint16_t*)pB2, b2, mask2, pO2,
            1856, 29, 400, 961, 61504, 1);
    }

    // ---- layer 3: fp16 single, K=3600, Kpad=3648, NC=57 ----
    {
        long tot = (long)14592 * (3648/8);
        k_gather<<<(unsigned)((tot + 255) / 256), 256>>>(pO2, pA3, selh3, selw3,
            31, 31, 400, 15, 225, 2, 3600, 3648, 14400, 14592);
        long wt = (long)896 * 3648;
        k_wcvt<<<(unsigned)((wt + 255) / 256), 256>>>(w3, pB3, 800, 400, 3600, 3648, 896);
        k_hmma<false><<<dim3(7, 114), 256, SMEM_HM>>>(
            (const uint16_t*)pA3, (const uint16_t*)pB3, b3, mask3, pO3,
            3648, 57, 800, 225, 14400, 1);
    }

    // ---- layer 4: dense 3x3 conv, SIMT fp32, NCHW output ----
    k_wt<<<(10 * 7200 + 255) / 256, 256>>>(w4, pW4, 10, 800);
    k_gemm<64, 4><<<dim3(169, 1), 256>>>(pO3, pW4, b4, nullptr,
                                         (float*)d_out,
                                         15, 15, 800, 10, 13, 13 * 13, 1, 7200, 0, 1);
}

// round 7
// speedup vs baseline: 1.8321x; 1.0123x over previous
#include <cuda_runtime.h>
#include <cuda_fp16.h>
#include <cstdint>

#define DINLINE __device__ __forceinline__

// ======================= scratch (device globals) =======================
__device__ __align__(16) float g_X [64*132*132*3];
__device__ __align__(16) float g_O1[64*65*65*200];
__device__ __align__(16) float g_O2[64*31*31*400];
__device__ __align__(16) float g_O3[64*15*15*800];
__device__ float g_W4t[7200*10];

// fp16 single-term everywhere: A[Npad][Kpad], B[OCpad][Kpad]
// L1: Kpad=64 Npad=270592 OCpad=256 ; L2: Kpad=1856 Npad=61696 OCpad=512
// L3: Kpad=3648 Npad=14592 OCpad=896
__device__ __align__(16) __half g_A1[(size_t)270592*64];
__device__ __align__(16) __half g_A2[(size_t)61696*1856];
__device__ __align__(16) __half g_A3[(size_t)14592*3648];
__device__ __align__(16) __half g_B1[(size_t)256*64];
__device__ __align__(16) __half g_B2[(size_t)512*1856];
__device__ __align__(16) __half g_B3[(size_t)896*3648];

// ======================= helpers =======================
DINLINE uint32_t smem_u32(const void* p){
    uint32_t a;
    asm("{ .reg .u64 t; cvta.to.shared.u64 t, %1; cvt.u32.u64 %0, t; }" : "=r"(a) : "l"(p));
    return a;
}
DINLINE void cp16(uint32_t dst, const void* src){
    asm volatile("cp.async.cg.shared.global [%0], [%1], 16;" :: "r"(dst), "l"(src));
}
DINLINE void cp_commit(){ asm volatile("cp.async.commit_group;" ::: "memory"); }
DINLINE void cp_wait1(){ asm volatile("cp.async.wait_group 1;" ::: "memory"); }

DINLINE void ldmx4(uint32_t r[4], uint32_t addr){
    asm volatile("ldmatrix.sync.aligned.m8n8.x4.shared.b16 {%0,%1,%2,%3}, [%4];"
        : "=r"(r[0]), "=r"(r[1]), "=r"(r[2]), "=r"(r[3]) : "r"(addr));
}
DINLINE void mma_fp16(float c[4], const uint32_t a[4], uint32_t b0, uint32_t b1){
    asm volatile("mma.sync.aligned.m16n8k16.row.col.f32.f16.f16.f32 "
        "{%0,%1,%2,%3}, {%4,%5,%6,%7}, {%8,%9}, {%0,%1,%2,%3};"
        : "+f"(c[0]), "+f"(c[1]), "+f"(c[2]), "+f"(c[3])
        : "r"(a[0]), "r"(a[1]), "r"(a[2]), "r"(a[3]), "r"(b0), "r"(b1));
}

// ======================= layout transforms =======================
__global__ void k_nchw2nhwc(const float* __restrict__ in, float* __restrict__ out,
                            int B, int C, int H, int W) {
    int idx = blockIdx.x * blockDim.x + threadIdx.x;
    if (idx >= B * C * H * W) return;
    int c = idx % C;
    int t = idx / C;
    int x = t % W; t /= W;
    int y = t % H; t /= H;
    out[idx] = in[((t * C + c) * H + y) * W + x];
}

__global__ void k_wt(const float* __restrict__ w, float* __restrict__ wt, int OC, int IC) {
    int idx = blockIdx.x * blockDim.x + threadIdx.x;
    if (idx >= OC * IC * 9) return;
    int oc  = idx % OC;
    int k   = idx / OC;
    int ic  = k % IC;
    int tap = k / IC;
    wt[idx] = w[(oc * IC + ic) * 9 + tap];
}

// weights: fp16 single, [OCpad][Kpad], k = tap*IC + ic
__global__ void k_wcvt(const float* __restrict__ W, __half* __restrict__ Bw,
                       int OC, int IC, int Klayer, int Kpad, int OCpad)
{
    long idx = (long)blockIdx.x*blockDim.x + threadIdx.x;
    if (idx >= (long)OCpad * Kpad) return;
    int oc = (int)(idx / Kpad);
    int kk = (int)(idx - (long)oc*Kpad);
    __half out = __float2half_rn(0.f);
    if (oc < OC && kk < Klayer){
        int tap = kk/IC, c = kk - tap*IC;
        out = __float2half_rn(W[((size_t)oc*IC + c)*9 + tap]);
    }
    Bw[idx] = out;
}

// layers 2/3 gather: fp16 single, A[n][Kpad]. IC % 8 == 0.
__global__ void k_gather(const float* __restrict__ In, __half* __restrict__ A,
                         const int* __restrict__ selh, const int* __restrict__ selw,
                         int IH, int IW, int IC, int OW, int P, int stride,
                         int Klayer, int Kpad, int Nreal, int Npad)
{
    int vecs = Kpad >> 3;
    long idx = (long)blockIdx.x*blockDim.x + threadIdx.x;
    if (idx >= (long)Npad * vecs) return;
    int n = (int)(idx / vecs);
    int v = (int)(idx - (long)n*vecs);
    int kk = v << 3;
    __half h[8];
    if (n < Nreal && kk < Klayer){
        int b = n / P, p = n - b*P;
        int oy = p / OW, ox = p - oy*OW;
        int ph = oy*stride + selh[p], pw = ox*stride + selw[p];
        int tap = kk / IC, c = kk - tap*IC;
        int ky = tap/3, kx = tap - ky*3;
        const float* src = In + ((size_t)((b*IH+ph+ky)*IW) + (pw+kx))*IC + c;
        float x[8];
        *(float4*)&x[0] = *(const float4*)src;
        *(float4*)&x[4] = *(const float4*)(src+4);
#pragma unroll
        for (int i=0;i<8;i++) h[i] = __float2half_rn(x[i]);
    } else {
#pragma unroll
        for (int i=0;i<8;i++) h[i] = __float2half_rn(0.f);
    }
    *(uint4*)(A + (size_t)n*Kpad + kk) = *(uint4*)h;
}

// layer 1 gather: fp16 single, Kpad=64, cols [0:27) valid
__global__ void k_gather1(const float* __restrict__ X, __half* __restrict__ A,
                          const int* __restrict__ selh, const int* __restrict__ selw)
{
    int n = blockIdx.x*blockDim.x + threadIdx.x;
    if (n >= 270592) return;
    __half row[64];
#pragma unroll
    for (int i=0;i<64;i++) row[i] = __float2half_rn(0.f);
    if (n < 270400){
        int b = n / 4225, p = n - b*4225;
        int oy = p/65, ox = p - oy*65;
        int ph = oy*2 + selh[p], pw = ox*2 + selw[p];
        const float* base = X + ((size_t)(b*132+ph)*132 + pw)*3;
#pragma unroll
        for (int ky=0;ky<3;ky++){
#pragma unroll
            for (int t=0;t<9;t++){
                row[ky*9 + t] = __float2half_rn(base[ky*396 + t]);
            }
        }
    }
    uint4* dst = (uint4*)(A + (size_t)n*64);
    uint4* s = (uint4*)row;
#pragma unroll
    for (int i=0;i<8;i++) dst[i] = s[i];
}

// ======================= HMMA GEMM (fp16, ks double-buffered) =======================
// CTA tile 128(n) x 128(oc), BK=64, 256 threads (8 warps, 4x2), 2 CTAs/SM.
// 3-stage ring of 32KB; fragments for ks+1 loaded before MMAs of ks.
static constexpr int STAGE = 32768;
static constexpr int SMEM_HM = 3 * STAGE;

__global__ __launch_bounds__(256, 2)
void k_hmma(const __half* __restrict__ A, const __half* __restrict__ B,
            const float* __restrict__ bias, const int* __restrict__ mask,
            float* __restrict__ Out,
            int ldK, int NC, int OC, int P, int Nreal, int relu)
{
    extern __shared__ char smem[];
    const uint32_t sb = smem_u32(smem);
    const int tid = threadIdx.x, lane = tid & 31, warp = tid >> 5;
    const int wm = warp >> 1, wn = warp & 1;   // 4 x 2 warp grid; warp tile 32 x 64

    const long ld = (long)ldK;
    const int l_row = tid >> 3, l_ch = tid & 7;
    const uint32_t l_soff = (uint32_t)(l_row*128 + ((l_ch ^ (l_row&7))<<4));
    const __half* Ag = A + (size_t)(blockIdx.y*128 + l_row) * ld + l_ch*8;
    const __half* Bg = B + (size_t)(blockIdx.x*128 + l_row) * ld + l_ch*8;
    const long ld32 = 32*ld;

    // per-warp read geometry (hoisted)
    const uint32_t rowA = (uint32_t)((wm*32 + (lane & 15)) * 128);
    const uint32_t rowB = (uint32_t)((wn*64 + (lane & 15)) * 128);
    const uint32_t chbase = (uint32_t)(lane >> 4);     // 0/1
    const uint32_t chxor  = (uint32_t)(lane & 7);

    float c[2][8][4];
#pragma unroll
    for (int i=0;i<2;i++)
#pragma unroll
        for (int j=0;j<8;j++)
#pragma unroll
            for (int k=0;k<4;k++) c[i][j][k] = 0.f;

    // prologue: chunks 0,1
    {
        uint32_t sA = sb, sB = sb + 16384;
#pragma unroll
        for (int i=0;i<4;i++) cp16(sA + l_soff + i*4096, Ag + i*ld32);
#pragma unroll
        for (int i=0;i<4;i++) cp16(sB + l_soff + i*4096, Bg + i*ld32);
        cp_commit();
        if (NC > 1){
            sA = sb + STAGE; sB = sA + 16384;
#pragma unroll
            for (int i=0;i<4;i++) cp16(sA + l_soff + i*4096, Ag + 64 + i*ld32);
#pragma unroll
            for (int i=0;i<4;i++) cp16(sB + l_soff + i*4096, Bg + 64 + i*ld32);
        }
        cp_commit();
    }

#pragma unroll 1
    for (int cc = 0; cc < NC; cc++){
        cp_wait1();
        __syncthreads();
        if (cc + 2 < NC){
            int c2 = cc + 2;
            uint32_t sA = sb + (c2 % 3)*STAGE, sB = sA + 16384;
#pragma unroll
            for (int i=0;i<4;i++) cp16(sA + l_soff + i*4096, Ag + c2*64 + i*ld32);
#pragma unroll
            for (int i=0;i<4;i++) cp16(sB + l_soff + i*4096, Bg + c2*64 + i*ld32);
        }
        cp_commit();

        const uint32_t sA = sb + (cc % 3)*STAGE;
        const uint32_t sB = sA + 16384;
        const uint32_t aA0 = sA + rowA, aA1 = aA0 + 16*128;
        const uint32_t aB0 = sB + rowB, aB1 = aB0 + 16*128,
                       aB2 = aB1 + 16*128, aB3 = aB2 + 16*128;

        uint32_t a[2][2][4], b[2][4][4];
        {   // load ks=0 into buffer 0
            const uint32_t ch = ((0*2 + chbase) ^ chxor) << 4;
            ldmx4(a[0][0], aA0 + ch); ldmx4(a[0][1], aA1 + ch);
            ldmx4(b[0][0], aB0 + ch); ldmx4(b[0][1], aB1 + ch);
            ldmx4(b[0][2], aB2 + ch); ldmx4(b[0][3], aB3 + ch);
        }
#pragma unroll
        for (int ks = 0; ks < 4; ks++){
            const int cur = ks & 1, nxt = cur ^ 1;
            if (ks < 3){   // prefetch ks+1 before MMAs of ks
                const uint32_t ch = (((ks+1)*2 + chbase) ^ chxor) << 4;
                ldmx4(a[nxt][0], aA0 + ch); ldmx4(a[nxt][1], aA1 + ch);
                ldmx4(b[nxt][0], aB0 + ch); ldmx4(b[nxt][1], aB1 + ch);
                ldmx4(b[nxt][2], aB2 + ch); ldmx4(b[nxt][3], aB3 + ch);
            }
#pragma unroll
            for (int mi = 0; mi < 2; mi++)
#pragma unroll
                for (int nj = 0; nj < 8; nj++)
                    mma_fp16(c[mi][nj], a[cur][mi],
                             b[cur][nj>>1][nj&1], b[cur][nj>>1][2+(nj&1)]);
        }
    }

    // ---- epilogue: mask, bias, relu, store NHWC ----
    const int gm0 = blockIdx.y*128 + wm*32;
    const int oc0 = blockIdx.x*128 + wn*64;
#pragma unroll
    for (int mi = 0; mi < 2; mi++){
#pragma unroll
        for (int half = 0; half < 2; half++){
            int n = gm0 + mi*16 + half*8 + (lane >> 2);
            if (n >= Nreal) continue;
            int mk = 1;
            if (mask){ int p = n % P; mk = mask[p]; }
            float* orow = Out + (size_t)n * OC;
#pragma unroll
            for (int nj = 0; nj < 8; nj++){
                int oc = oc0 + nj*8 + (lane & 3)*2;
                float v0 = (mk ? c[mi][nj][half*2+0] : 0.f) + __ldg(&bias[oc < OC ? oc : 0]);
                float v1 = (mk ? c[mi][nj][half*2+1] : 0.f) + __ldg(&bias[(oc+1) < OC ? (oc+1) : 0]);
                if (relu){ v0 = fmaxf(v0, 0.f); v1 = fmaxf(v1, 0.f); }
                if (oc + 1 < OC){
                    float2 v = {v0, v1};
                    *(float2*)(orow + oc) = v;
                } else if (oc < OC){
                    orow[oc] = v0;
                }
            }
        }
    }
}

// ======================= SIMT GEMM (layer 4 only) =======================
#define BN 64
#define BK 16
#define TN 4
template <int BMp, int TMp>
__global__ __launch_bounds__(256)
void k_gemm(const float* __restrict__ In, const float* __restrict__ Wt,
            const float* __restrict__ bias,
            const int* __restrict__ mask,
            float* __restrict__ Out,
            int IH, int IW, int IC, int OC,
            int OW, int P, int stride, int Ktot,
            int relu, int out_nchw)
{
    __shared__ float As[BK][BN + 1];
    __shared__ float Ws[BK][BMp];
    __shared__ int   s_base[BN];

    const int tid = threadIdx.x;
    const int n0  = blockIdx.x * BN;
    const int m0  = blockIdx.y * BMp;

    if (tid < BN) {
        int n  = n0 + tid;
        int b  = n / P;
        int p  = n - b * P;
        int oy = p / OW;
        int ox = p - oy * OW;
        s_base[tid] = ((b * IH + oy*stride) * IW + ox*stride) * IC;
    }
    __syncthreads();

    const int tx = tid & 15;
    const int ty = tid >> 4;

    constexpr int KSTEP = 256 / BMp;
    const int w_mm  = tid % BMp;
    const int w_kk0 = tid / BMp;
    const int a_kk  = tid & (BK - 1);
    const int a_nn0 = tid >> 4;

    float acc[TMp][TN];
#pragma unroll
    for (int i = 0; i < TMp; i++)
#pragma unroll
        for (int j = 0; j < TN; j++) acc[i][j] = 0.f;

    for (int k0 = 0; k0 < Ktot; k0 += BK) {
#pragma unroll
        for (int r = 0; r < BK / KSTEP; r++) {
            int kk = w_kk0 + r * KSTEP;
            int k  = k0 + kk;
            int m  = m0 + w_mm;
            Ws[kk][w_mm] = (k < Ktot && m < OC) ? Wt[k * OC + m] : 0.f;
        }
        {
            int  k   = k0 + a_kk;
            bool ok  = (k < Ktot);
            int  off = 0;
            if (ok) {
                int c   = k % IC;
                int tap = k / IC;
                int ky  = tap / 3, kx = tap - ky * 3;
                off = (ky * IW + kx) * IC + c;
            }
#pragma unroll
            for (int r = 0; r < 4; r++) {
                int nn = a_nn0 + 16 * r;
                As[a_kk][nn] = ok ? In[s_base[nn] + off] : 0.f;
            }
        }
        __syncthreads();

#pragma unroll
        for (int kk = 0; kk < BK; kk++) {
            float ra[TN], rb[TMp];
#pragma unroll
            for (int j = 0; j < TN; j++)  ra[j] = As[kk][tx * TN + j];
#pragma unroll
            for (int i = 0; i < TMp; i++) rb[i] = Ws[kk][ty * TMp + i];
#pragma unroll
            for (int i = 0; i < TMp; i++)
#pragma unroll
                for (int j = 0; j < TN; j++)
                    acc[i][j] = fmaf(rb[i], ra[j], acc[i][j]);
        }
        __syncthreads();
    }

#pragma unroll
    for (int j = 0; j < TN; j++) {
        int n = n0 + tx * TN + j;
        int b = n / P;
        int p = n - b * P;
        int mk = mask ? mask[p] : 1;
#pragma unroll
        for (int i = 0; i < TMp; i++) {
            int m = m0 + ty * TMp + i;
            if (m < OC) {
                float v = mk ? acc[i][j] : 0.f;
                v += __ldg(&bias[m]);
                if (relu) v = fmaxf(v, 0.f);
                if (out_nchw)
                    Out[(b * OC + m) * P + p] = v;
                else
                    Out[n * OC + m] = v;
            }
        }
    }
}

// ======================= launch =======================
extern "C" void kernel_launch(void* const* d_in, const int* in_sizes, int n_in,
                              void* d_out, int out_size) {
    const float* x     = (const float*)d_in[0];
    const float* w1    = (const float*)d_in[1];
    const float* b1    = (const float*)d_in[2];
    const float* w2    = (const float*)d_in[3];
    const float* b2    = (const float*)d_in[4];
    const float* w3    = (const float*)d_in[5];
    const float* b3    = (const float*)d_in[6];
    const float* w4    = (const float*)d_in[7];
    const float* b4    = (const float*)d_in[8];
    const int*   selh1 = (const int*)d_in[9];
    const int*   selw1 = (const int*)d_in[10];
    const int*   mask1 = (const int*)d_in[11];
    const int*   selh2 = (const int*)d_in[12];
    const int*   selw2 = (const int*)d_in[13];
    const int*   mask2 = (const int*)d_in[14];
    const int*   selh3 = (const int*)d_in[15];
    const int*   selw3 = (const int*)d_in[16];
    const int*   mask3 = (const int*)d_in[17];

    float *pX, *pO1, *pO2, *pO3, *pW4;
    __half *pA1, *pA2, *pA3, *pB1, *pB2, *pB3;
    cudaGetSymbolAddress((void**)&pX,  g_X);
    cudaGetSymbolAddress((void**)&pO1, g_O1);
    cudaGetSymbolAddress((void**)&pO2, g_O2);
    cudaGetSymbolAddress((void**)&pO3, g_O3);
    cudaGetSymbolAddress((void**)&pW4, g_W4t);
    cudaGetSymbolAddress((void**)&pA1, g_A1);
    cudaGetSymbolAddress((void**)&pA2, g_A2);
    cudaGetSymbolAddress((void**)&pA3, g_A3);
    cudaGetSymbolAddress((void**)&pB1, g_B1);
    cudaGetSymbolAddress((void**)&pB2, g_B2);
    cudaGetSymbolAddress((void**)&pB3, g_B3);

    cudaFuncSetAttribute(k_hmma, cudaFuncAttributeMaxDynamicSharedMemorySize, SMEM_HM);

    // x -> NHWC
    {
        int tot = 64 * 3 * 132 * 132;
        k_nchw2nhwc<<<(tot + 255) / 256, 256>>>(x, pX, 64, 3, 132, 132);
    }

    // ---- layer 1: fp16 single, K=27, Kpad=64, NC=1 ----
    k_gather1<<<(270592 + 255) / 256, 256>>>(pX, pA1, selh1, selw1);
    k_wcvt<<<(256*64 + 255) / 256, 256>>>(w1, pB1, 200, 3, 27, 64, 256);
    k_hmma<<<dim3(2, 2114), 256, SMEM_HM>>>(pA1, pB1, b1, mask1, pO1,
                                            64, 1, 200, 4225, 270400, 1);

    // ---- layer 2: fp16 single, K=1800, Kpad=1856, NC=29 ----
    {
        long tot = (long)61696 * (1856/8);
        k_gather<<<(unsigned)((tot + 255) / 256), 256>>>(pO1, pA2, selh2, selw2,
            65, 65, 200, 31, 961, 2, 1800, 1856, 61504, 61696);
        long wt = (long)512 * 1856;
        k_wcvt<<<(unsigned)((wt + 255) / 256), 256>>>(w2, pB2, 400, 200, 1800, 1856, 512);
        k_hmma<<<dim3(4, 482), 256, SMEM_HM>>>(pA2, pB2, b2, mask2, pO2,
                                               1856, 29, 400, 961, 61504, 1);
    }

    // ---- layer 3: fp16 single, K=3600, Kpad=3648, NC=57 ----
    {
        long tot = (long)14592 * (3648/8);
        k_gather<<<(unsigned)((tot + 255) / 256), 256>>>(pO2, pA3, selh3, selw3,
            31, 31, 400, 15, 225, 2, 3600, 3648, 14400, 14592);
        long wt = (long)896 * 3648;
        k_wcvt<<<(unsigned)((wt + 255) / 256), 256>>>(w3, pB3, 800, 400, 3600, 3648, 896);
        k_hmma<<<dim3(7, 114), 256, SMEM_HM>>>(pA3, pB3, b3, mask3, pO3,
                                               3648, 57, 800, 225, 14400, 1);
    }

    // ---- layer 4: dense 3x3 conv, SIMT fp32, NCHW output ----
    k_wt<<<(10 * 7200 + 255) / 256, 256>>>(w4, pW4, 10, 800);
    k_gemm<64, 4><<<dim3(169, 1), 256>>>(pO3, pW4, b4, nullptr,
                                         (float*)d_out,
                                         15, 15, 800, 10, 13, 13 * 13, 1, 7200, 0, 1);
}

// round 8
// speedup vs baseline: 1.9546x; 1.0669x over previous
#include <cuda_runtime.h>
#include <cuda_fp16.h>
#include <cstdint>

#define DINLINE __device__ __forceinline__

// ======================= scratch (device globals) =======================
__device__ __align__(16) float  g_X [64*132*132*3];     // x NHWC fp32
__device__ __align__(16) __half g_O1[(size_t)64*65*65*200]; // L1 out fp16 NHWC
__device__ __align__(16) __half g_O2[(size_t)64*31*31*400]; // L2 out fp16 NHWC
__device__ __align__(16) float  g_O3[(size_t)64*15*15*800]; // L3 out fp32 NHWC
__device__ float g_W4t[7200*10];

// L1 im2col (kept; tiny): A1[Npad=270592][64]
__device__ __align__(16) __half g_A1[(size_t)270592*64];
// weights fp16 [OCpad][Kpad]
__device__ __align__(16) __half g_B1[(size_t)256*64];
__device__ __align__(16) __half g_B2[(size_t)512*1856];
__device__ __align__(16) __half g_B3[(size_t)896*3648];

// ======================= helpers =======================
DINLINE uint32_t smem_u32(const void* p){
    uint32_t a;
    asm("{ .reg .u64 t; cvta.to.shared.u64 t, %1; cvt.u32.u64 %0, t; }" : "=r"(a) : "l"(p));
    return a;
}
DINLINE void cp16(uint32_t dst, const void* src){
    asm volatile("cp.async.cg.shared.global [%0], [%1], 16;" :: "r"(dst), "l"(src));
}
DINLINE void cp16z(uint32_t dst, const void* src, uint32_t srcsize){ // zero-fill when srcsize=0
    asm volatile("cp.async.cg.shared.global [%0], [%1], 16, %2;" :: "r"(dst), "l"(src), "r"(srcsize));
}
DINLINE void cp_commit(){ asm volatile("cp.async.commit_group;" ::: "memory"); }
DINLINE void cp_wait1(){ asm volatile("cp.async.wait_group 1;" ::: "memory"); }

DINLINE void ldmx4(uint32_t r[4], uint32_t addr){
    asm volatile("ldmatrix.sync.aligned.m8n8.x4.shared.b16 {%0,%1,%2,%3}, [%4];"
        : "=r"(r[0]), "=r"(r[1]), "=r"(r[2]), "=r"(r[3]) : "r"(addr));
}
DINLINE void mma_fp16(float c[4], const uint32_t a[4], uint32_t b0, uint32_t b1){
    asm volatile("mma.sync.aligned.m16n8k16.row.col.f32.f16.f16.f32 "
        "{%0,%1,%2,%3}, {%4,%5,%6,%7}, {%8,%9}, {%0,%1,%2,%3};"
        : "+f"(c[0]), "+f"(c[1]), "+f"(c[2]), "+f"(c[3])
        : "r"(a[0]), "r"(a[1]), "r"(a[2]), "r"(a[3]), "r"(b0), "r"(b1));
}

// ======================= layout transforms =======================
__global__ void k_nchw2nhwc(const float* __restrict__ in, float* __restrict__ out,
                            int B, int C, int H, int W) {
    int idx = blockIdx.x * blockDim.x + threadIdx.x;
    if (idx >= B * C * H * W) return;
    int c = idx % C;
    int t = idx / C;
    int x = t % W; t /= W;
    int y = t % H; t /= H;
    out[idx] = in[((t * C + c) * H + y) * W + x];
}

__global__ void k_wt(const float* __restrict__ w, float* __restrict__ wt, int OC, int IC) {
    int idx = blockIdx.x * blockDim.x + threadIdx.x;
    if (idx >= OC * IC * 9) return;
    int oc  = idx % OC;
    int k   = idx / OC;
    int ic  = k % IC;
    int tap = k / IC;
    wt[idx] = w[(oc * IC + ic) * 9 + tap];
}

// weights: fp16 single, [OCpad][Kpad], k = tap*IC + ic
__global__ void k_wcvt(const float* __restrict__ W, __half* __restrict__ Bw,
                       int OC, int IC, int Klayer, int Kpad, int OCpad)
{
    long idx = (long)blockIdx.x*blockDim.x + threadIdx.x;
    if (idx >= (long)OCpad * Kpad) return;
    int oc = (int)(idx / Kpad);
    int kk = (int)(idx - (long)oc*Kpad);
    __half out = __float2half_rn(0.f);
    if (oc < OC && kk < Klayer){
        int tap = kk/IC, c = kk - tap*IC;
        out = __float2half_rn(W[((size_t)oc*IC + c)*9 + tap]);
    }
    Bw[idx] = out;
}

// layer 1 gather: fp16, Kpad=64, cols [0:27) valid
__global__ void k_gather1(const float* __restrict__ X, __half* __restrict__ A,
                          const int* __restrict__ selh, const int* __restrict__ selw)
{
    int n = blockIdx.x*blockDim.x + threadIdx.x;
    if (n >= 270592) return;
    __half row[64];
#pragma unroll
    for (int i=0;i<64;i++) row[i] = __float2half_rn(0.f);
    if (n < 270400){
        int b = n / 4225, p = n - b*4225;
        int oy = p/65, ox = p - oy*65;
        int ph = oy*2 + selh[p], pw = ox*2 + selw[p];
        const float* base = X + ((size_t)(b*132+ph)*132 + pw)*3;
#pragma unroll
        for (int ky=0;ky<3;ky++){
#pragma unroll
            for (int t=0;t<9;t++){
                row[ky*9 + t] = __float2half_rn(base[ky*396 + t]);
            }
        }
    }
    uint4* dst = (uint4*)(A + (size_t)n*64);
    uint4* s = (uint4*)row;
#pragma unroll
    for (int i=0;i<8;i++) dst[i] = s[i];
}

// ======================= HMMA GEMM (optionally fused im2col A-load) =======================
// CTA tile 128(n) x 128(oc), BK=64, 256 threads (8 warps, 4x2), 2 CTAs/SM.
// 3-stage ring of 32KB (+512B s_base).
static constexpr int STAGE = 32768;
static constexpr int SMEM_HM = 3 * STAGE + 512;

template <bool FUSED, bool OUT_HALF>
__global__ __launch_bounds__(256, 2)
void k_hmma(const __half* __restrict__ A, const __half* __restrict__ B,
            const float* __restrict__ bias, const int* __restrict__ mask,
            void* __restrict__ Outv,
            int Kpad, int NC, int OC, int P, int Nreal, int relu,
            const __half* __restrict__ Src, const int* __restrict__ selh,
            const int* __restrict__ selw, int IW, int ICp, int OW,
            int stride, int Klayer)
{
    extern __shared__ char smem[];
    const uint32_t sb = smem_u32(smem);
    int* s_base = (int*)(smem + 3*STAGE);
    const int tid = threadIdx.x, lane = tid & 31, warp = tid >> 5;
    const int wm = warp >> 1, wn = warp & 1;   // 4 x 2 warp grid; warp tile 32 x 64

    const long ld = (long)Kpad;
    const int l_row = tid >> 3, l_ch = tid & 7;
    const uint32_t l_soff = (uint32_t)(l_row*128 + ((l_ch ^ (l_row&7))<<4));
    const __half* Ag = A + (size_t)(blockIdx.y*128 + l_row) * ld + l_ch*8; // non-fused only
    const __half* Bg = B + (size_t)(blockIdx.x*128 + l_row) * ld + l_ch*8;
    const long ld32 = 32*ld;

    if (FUSED){
        if (tid < 128){
            int n = blockIdx.y*128 + tid;
            if (n >= Nreal) n = Nreal - 1;            // clamp; masked in epilogue
            int b = n / P, p = n - b*P;
            int oy = p / OW, ox = p - oy*OW;
            int ph = oy*stride + selh[p], pw = ox*stride + selw[p];
            s_base[tid] = (b*IW + ph)*IW + pw;        // square grid: IH==IW
        }
        __syncthreads();
    }

    // fused/non-fused A chunk loader
    auto loadA = [&](int cc, uint32_t sA){
        if (FUSED){
            int k = cc*64 + l_ch*8;
            uint32_t sz = (k < Klayer) ? 16u : 0u;
            long off = 0;
            if (sz){
                int tap = k / ICp, c = k - tap*ICp;
                int ky = tap/3, kx = tap - 3*ky;
                off = (long)(ky*IW + kx)*ICp + c;
            }
#pragma unroll
            for (int i=0;i<4;i++){
                int row = l_row + i*32;
                const __half* src = Src + (size_t)s_base[row]*ICp + off;
                cp16z(sA + l_soff + i*4096, src, sz);
            }
        } else {
#pragma unroll
            for (int i=0;i<4;i++) cp16(sA + l_soff + i*4096, Ag + cc*64 + i*ld32);
        }
    };
    auto loadB = [&](int cc, uint32_t sB){
#pragma unroll
        for (int i=0;i<4;i++) cp16(sB + l_soff + i*4096, Bg + cc*64 + i*ld32);
    };

    // per-warp read geometry
    const uint32_t rowA = (uint32_t)((wm*32 + (lane & 15)) * 128);
    const uint32_t rowB = (uint32_t)((wn*64 + (lane & 15)) * 128);
    const uint32_t chbase = (uint32_t)(lane >> 4);
    const uint32_t chxor  = (uint32_t)(lane & 7);

    float c[2][8][4];
#pragma unroll
    for (int i=0;i<2;i++)
#pragma unroll
        for (int j=0;j<8;j++)
#pragma unroll
            for (int k=0;k<4;k++) c[i][j][k] = 0.f;

    // prologue: chunks 0,1
    loadA(0, sb);           loadB(0, sb + 16384);           cp_commit();
    if (NC > 1){ loadA(1, sb + STAGE); loadB(1, sb + STAGE + 16384); }
    cp_commit();

#pragma unroll 1
    for (int cc = 0; cc < NC; cc++){
        cp_wait1();
        __syncthreads();
        if (cc + 2 < NC){
            int c2 = cc + 2;
            uint32_t sA = sb + (c2 % 3)*STAGE;
            loadA(c2, sA); loadB(c2, sA + 16384);
        }
        cp_commit();

        const uint32_t sA = sb + (cc % 3)*STAGE;
        const uint32_t sB = sA + 16384;
        const uint32_t aA0 = sA + rowA, aA1 = aA0 + 16*128;
        const uint32_t aB0 = sB + rowB, aB1 = aB0 + 16*128,
                       aB2 = aB1 + 16*128, aB3 = aB2 + 16*128;

        uint32_t a[2][2][4], b[2][4][4];
        {
            const uint32_t ch = (chbase ^ chxor) << 4;
            ldmx4(a[0][0], aA0 + ch); ldmx4(a[0][1], aA1 + ch);
            ldmx4(b[0][0], aB0 + ch); ldmx4(b[0][1], aB1 + ch);
            ldmx4(b[0][2], aB2 + ch); ldmx4(b[0][3], aB3 + ch);
        }
#pragma unroll
        for (int ks = 0; ks < 4; ks++){
            const int cur = ks & 1, nxt = cur ^ 1;
            if (ks < 3){
                const uint32_t ch = (((ks+1)*2 + chbase) ^ chxor) << 4;
                ldmx4(a[nxt][0], aA0 + ch); ldmx4(a[nxt][1], aA1 + ch);
                ldmx4(b[nxt][0], aB0 + ch); ldmx4(b[nxt][1], aB1 + ch);
                ldmx4(b[nxt][2], aB2 + ch); ldmx4(b[nxt][3], aB3 + ch);
            }
#pragma unroll
            for (int mi = 0; mi < 2; mi++)
#pragma unroll
                for (int nj = 0; nj < 8; nj++)
                    mma_fp16(c[mi][nj], a[cur][mi],
                             b[cur][nj>>1][nj&1], b[cur][nj>>1][2+(nj&1)]);
        }
    }

    // ---- epilogue: mask, bias, relu, store NHWC (fp16 or fp32) ----
    const int gm0 = blockIdx.y*128 + wm*32;
    const int oc0 = blockIdx.x*128 + wn*64;
#pragma unroll
    for (int mi = 0; mi < 2; mi++){
#pragma unroll
        for (int half = 0; half < 2; half++){
            int n = gm0 + mi*16 + half*8 + (lane >> 2);
            if (n >= Nreal) continue;
            int mk = 1;
            if (mask){ int p = n % P; mk = mask[p]; }
#pragma unroll
            for (int nj = 0; nj < 8; nj++){
                int oc = oc0 + nj*8 + (lane & 3)*2;
                if (oc < OC){                         // OC even, oc even -> pair fits
                    float v0 = (mk ? c[mi][nj][half*2+0] : 0.f) + __ldg(&bias[oc]);
                    float v1 = (mk ? c[mi][nj][half*2+1] : 0.f) + __ldg(&bias[oc+1]);
                    if (relu){ v0 = fmaxf(v0, 0.f); v1 = fmaxf(v1, 0.f); }
                    if (OUT_HALF){
                        __half2* orow = (__half2*)((__half*)Outv + (size_t)n * OC + oc);
                        *orow = __floats2half2_rn(v0, v1);
                    } else {
                        float2 v = {v0, v1};
                        *(float2*)((float*)Outv + (size_t)n * OC + oc) = v;
                    }
                }
            }
        }
    }
}

// ======================= SIMT GEMM (layer 4 only) =======================
#define BN 64
#define BK 16
#define TN 4
template <int BMp, int TMp>
__global__ __launch_bounds__(256)
void k_gemm(const float* __restrict__ In, const float* __restrict__ Wt,
            const float* __restrict__ bias,
            const int* __restrict__ mask,
            float* __restrict__ Out,
            int IH, int IW, int IC, int OC,
            int OW, int P, int stride, int Ktot,
            int relu, int out_nchw)
{
    __shared__ float As[BK][BN + 1];
    __shared__ float Ws[BK][BMp];
    __shared__ int   s_base[BN];

    const int tid = threadIdx.x;
    const int n0  = blockIdx.x * BN;
    const int m0  = blockIdx.y * BMp;

    if (tid < BN) {
        int n  = n0 + tid;
        int b  = n / P;
        int p  = n - b * P;
        int oy = p / OW;
        int ox = p - oy * OW;
        s_base[tid] = ((b * IH + oy*stride) * IW + ox*stride) * IC;
    }
    __syncthreads();

    const int tx = tid & 15;
    const int ty = tid >> 4;

    constexpr int KSTEP = 256 / BMp;
    const int w_mm  = tid % BMp;
    const int w_kk0 = tid / BMp;
    const int a_kk  = tid & (BK - 1);
    const int a_nn0 = tid >> 4;

    float acc[TMp][TN];
#pragma unroll
    for (int i = 0; i < TMp; i++)
#pragma unroll
        for (int j = 0; j < TN; j++) acc[i][j] = 0.f;

    for (int k0 = 0; k0 < Ktot; k0 += BK) {
#pragma unroll
        for (int r = 0; r < BK / KSTEP; r++) {
            int kk = w_kk0 + r * KSTEP;
            int k  = k0 + kk;
            int m  = m0 + w_mm;
            Ws[kk][w_mm] = (k < Ktot && m < OC) ? Wt[k * OC + m] : 0.f;
        }
        {
            int  k   = k0 + a_kk;
            bool ok  = (k < Ktot);
            int  off = 0;
            if (ok) {
                int c   = k % IC;
                int tap = k / IC;
                int ky  = tap / 3, kx = tap - ky * 3;
                off = (ky * IW + kx) * IC + c;
            }
#pragma unroll
            for (int r = 0; r < 4; r++) {
                int nn = a_nn0 + 16 * r;
                As[a_kk][nn] = ok ? In[s_base[nn] + off] : 0.f;
            }
        }
        __syncthreads();

#pragma unroll
        for (int kk = 0; kk < BK; kk++) {
            float ra[TN], rb[TMp];
#pragma unroll
            for (int j = 0; j < TN; j++)  ra[j] = As[kk][tx * TN + j];
#pragma unroll
            for (int i = 0; i < TMp; i++) rb[i] = Ws[kk][ty * TMp + i];
#pragma unroll
            for (int i = 0; i < TMp; i++)
#pragma unroll
                for (int j = 0; j < TN; j++)
                    acc[i][j] = fmaf(rb[i], ra[j], acc[i][j]);
        }
        __syncthreads();
    }

#pragma unroll
    for (int j = 0; j < TN; j++) {
        int n = n0 + tx * TN + j;
        int b = n / P;
        int p = n - b * P;
        int mk = mask ? mask[p] : 1;
#pragma unroll
        for (int i = 0; i < TMp; i++) {
            int m = m0 + ty * TMp + i;
            if (m < OC) {
                float v = mk ? acc[i][j] : 0.f;
                v += __ldg(&bias[m]);
                if (relu) v = fmaxf(v, 0.f);
                if (out_nchw)
                    Out[(b * OC + m) * P + p] = v;
                else
                    Out[n * OC + m] = v;
            }
        }
    }
}

// ======================= launch =======================
extern "C" void kernel_launch(void* const* d_in, const int* in_sizes, int n_in,
                              void* d_out, int out_size) {
    const float* x     = (const float*)d_in[0];
    const float* w1    = (const float*)d_in[1];
    const float* b1    = (const float*)d_in[2];
    const float* w2    = (const float*)d_in[3];
    const float* b2    = (const float*)d_in[4];
    const float* w3    = (const float*)d_in[5];
    const float* b3    = (const float*)d_in[6];
    const float* w4    = (const float*)d_in[7];
    const float* b4    = (const float*)d_in[8];
    const int*   selh1 = (const int*)d_in[9];
    const int*   selw1 = (const int*)d_in[10];
    const int*   mask1 = (const int*)d_in[11];
    const int*   selh2 = (const int*)d_in[12];
    const int*   selw2 = (const int*)d_in[13];
    const int*   mask2 = (const int*)d_in[14];
    const int*   selh3 = (const int*)d_in[15];
    const int*   selw3 = (const int*)d_in[16];
    const int*   mask3 = (const int*)d_in[17];

    float *pX, *pO3, *pW4;
    __half *pO1, *pO2, *pA1, *pB1, *pB2, *pB3;
    cudaGetSymbolAddress((void**)&pX,  g_X);
    cudaGetSymbolAddress((void**)&pO1, g_O1);
    cudaGetSymbolAddress((void**)&pO2, g_O2);
    cudaGetSymbolAddress((void**)&pO3, g_O3);
    cudaGetSymbolAddress((void**)&pW4, g_W4t);
    cudaGetSymbolAddress((void**)&pA1, g_A1);
    cudaGetSymbolAddress((void**)&pB1, g_B1);
    cudaGetSymbolAddress((void**)&pB2, g_B2);
    cudaGetSymbolAddress((void**)&pB3, g_B3);

    cudaFuncSetAttribute((const void*)k_hmma<false,true>,
                         cudaFuncAttributeMaxDynamicSharedMemorySize, SMEM_HM);
    cudaFuncSetAttribute((const void*)k_hmma<true,true>,
                         cudaFuncAttributeMaxDynamicSharedMemorySize, SMEM_HM);
    cudaFuncSetAttribute((const void*)k_hmma<true,false>,
                         cudaFuncAttributeMaxDynamicSharedMemorySize, SMEM_HM);

    // x -> NHWC
    {
        int tot = 64 * 3 * 132 * 132;
        k_nchw2nhwc<<<(tot + 255) / 256, 256>>>(x, pX, 64, 3, 132, 132);
    }

    // ---- layer 1: im2col + GEMM (non-fused), fp16 out ----
    k_gather1<<<(270592 + 255) / 256, 256>>>(pX, pA1, selh1, selw1);
    k_wcvt<<<(256*64 + 255) / 256, 256>>>(w1, pB1, 200, 3, 27, 64, 256);
    k_hmma<false,true><<<dim3(2, 2114), 256, SMEM_HM>>>(
        pA1, pB1, b1, mask1, pO1, 64, 1, 200, 4225, 270400, 1,
        nullptr, nullptr, nullptr, 0, 0, 0, 0, 0);

    // ---- layer 2: fused gather GEMM, K=1800, Kpad=1856, NC=29, fp16 out ----
    {
        long wt = (long)512 * 1856;
        k_wcvt<<<(unsigned)((wt + 255) / 256), 256>>>(w2, pB2, 400, 200, 1800, 1856, 512);
        k_hmma<true,true><<<dim3(4, 482), 256, SMEM_HM>>>(
            nullptr, pB2, b2, mask2, pO2, 1856, 29, 400, 961, 61504, 1,
            pO1, selh2, selw2, 65, 200, 31, 2, 1800);
    }

    // ---- layer 3: fused gather GEMM, K=3600, Kpad=3648, NC=57, fp32 out ----
    {
        long wt = (long)896 * 3648;
        k_wcvt<<<(unsigned)((wt + 255) / 256), 256>>>(w3, pB3, 800, 400, 3600, 3648, 896);
        k_hmma<true,false><<<dim3(7, 114), 256, SMEM_HM>>>(
            nullptr, pB3, b3, mask3, pO3, 3648, 57, 800, 225, 14400, 1,
            pO2, selh3, selw3, 31, 400, 15, 2, 3600);
    }

    // ---- layer 4: dense 3x3 conv, SIMT fp32, NCHW output ----
    k_wt<<<(10 * 7200 + 255) / 256, 256>>>(w4, pW4, 10, 800);
    k_gemm<64, 4><<<dim3(169, 1), 256>>>(pO3, pW4, b4, nullptr,
                                         (float*)d_out,
                                         15, 15, 800, 10, 13, 13 * 13, 1, 7200, 0, 1);
}

// round 9
// speedup vs baseline: 4.0793x; 2.0870x over previous
#include <cuda_runtime.h>
#include <cuda_fp16.h>
#include <cstdint>

#define DINLINE __device__ __forceinline__

// ======================= scratch (device globals) =======================
__device__ __align__(16) float  g_X [64*132*132*3];         // x NHWC fp32
__device__ __align__(16) __half g_O1[(size_t)64*65*65*200]; // L1 out fp16 NHWC
__device__ __align__(16) __half g_O2[(size_t)64*31*31*400]; // L2 out fp16 NHWC
__device__ __align__(16) __half g_O3[(size_t)64*15*15*800]; // L3 out fp16 NHWC

// L1 im2col (kept; tiny): A1[Npad=270592][64]
__device__ __align__(16) __half g_A1[(size_t)270592*64];
// weights fp16 [OCpad][Kpad]
__device__ __align__(16) __half g_B1[(size_t)256*64];
__device__ __align__(16) __half g_B2[(size_t)512*1856];
__device__ __align__(16) __half g_B3[(size_t)896*3648];
__device__ __align__(16) __half g_B4[(size_t)64*7232];

// ======================= helpers =======================
DINLINE uint32_t smem_u32(const void* p){
    uint32_t a;
    asm("{ .reg .u64 t; cvta.to.shared.u64 t, %1; cvt.u32.u64 %0, t; }" : "=r"(a) : "l"(p));
    return a;
}
DINLINE void cp16(uint32_t dst, const void* src){
    asm volatile("cp.async.cg.shared.global [%0], [%1], 16;" :: "r"(dst), "l"(src));
}
DINLINE void cp16z(uint32_t dst, const void* src, uint32_t srcsize){
    asm volatile("cp.async.cg.shared.global [%0], [%1], 16, %2;" :: "r"(dst), "l"(src), "r"(srcsize));
}
DINLINE void cp_commit(){ asm volatile("cp.async.commit_group;" ::: "memory"); }
DINLINE void cp_wait1(){ asm volatile("cp.async.wait_group 1;" ::: "memory"); }

DINLINE void ldmx4(uint32_t r[4], uint32_t addr){
    asm volatile("ldmatrix.sync.aligned.m8n8.x4.shared.b16 {%0,%1,%2,%3}, [%4];"
        : "=r"(r[0]), "=r"(r[1]), "=r"(r[2]), "=r"(r[3]) : "r"(addr));
}
DINLINE void mma_fp16(float c[4], const uint32_t a[4], uint32_t b0, uint32_t b1){
    asm volatile("mma.sync.aligned.m16n8k16.row.col.f32.f16.f16.f32 "
        "{%0,%1,%2,%3}, {%4,%5,%6,%7}, {%8,%9}, {%0,%1,%2,%3};"
        : "+f"(c[0]), "+f"(c[1]), "+f"(c[2]), "+f"(c[3])
        : "r"(a[0]), "r"(a[1]), "r"(a[2]), "r"(a[3]), "r"(b0), "r"(b1));
}

// ======================= layout transforms =======================
__global__ void k_nchw2nhwc(const float* __restrict__ in, float* __restrict__ out,
                            int B, int C, int H, int W) {
    int idx = blockIdx.x * blockDim.x + threadIdx.x;
    if (idx >= B * C * H * W) return;
    int c = idx % C;
    int t = idx / C;
    int x = t % W; t /= W;
    int y = t % H; t /= H;
    out[idx] = in[((t * C + c) * H + y) * W + x];
}

// weights: fp16, [OCpad][Kpad], k = tap*IC + ic
__global__ void k_wcvt(const float* __restrict__ W, __half* __restrict__ Bw,
                       int OC, int IC, int Klayer, int Kpad, int OCpad)
{
    long idx = (long)blockIdx.x*blockDim.x + threadIdx.x;
    if (idx >= (long)OCpad * Kpad) return;
    int oc = (int)(idx / Kpad);
    int kk = (int)(idx - (long)oc*Kpad);
    __half out = __float2half_rn(0.f);
    if (oc < OC && kk < Klayer){
        int tap = kk/IC, c = kk - tap*IC;
        out = __float2half_rn(W[((size_t)oc*IC + c)*9 + tap]);
    }
    Bw[idx] = out;
}

// layer 1 gather: fp16, Kpad=64, cols [0:27) valid
__global__ void k_gather1(const float* __restrict__ X, __half* __restrict__ A,
                          const int* __restrict__ selh, const int* __restrict__ selw)
{
    int n = blockIdx.x*blockDim.x + threadIdx.x;
    if (n >= 270592) return;
    __half row[64];
#pragma unroll
    for (int i=0;i<64;i++) row[i] = __float2half_rn(0.f);
    if (n < 270400){
        int b = n / 4225, p = n - b*4225;
        int oy = p/65, ox = p - oy*65;
        int ph = oy*2 + selh[p], pw = ox*2 + selw[p];
        const float* base = X + ((size_t)(b*132+ph)*132 + pw)*3;
#pragma unroll
        for (int ky=0;ky<3;ky++){
#pragma unroll
            for (int t=0;t<9;t++){
                row[ky*9 + t] = __float2half_rn(base[ky*396 + t]);
            }
        }
    }
    uint4* dst = (uint4*)(A + (size_t)n*64);
    uint4* s = (uint4*)row;
#pragma unroll
    for (int i=0;i<8;i++) dst[i] = s[i];
}

// ======================= HMMA GEMM =======================
// CTA tile 128(n) x NT(oc), BK=64, 256 threads (8 warps, 4x2), 2 CTAs/SM.
// 3-stage ring (uniform 32KB spacing); optional fused im2col A-load.
// OUTM: 0 = fp32 NHWC, 1 = fp16 NHWC, 2 = fp32 NCHW (flattened)
static constexpr int STAGE = 32768;
static constexpr int SMEM_HM = 3 * STAGE + 512;

template <bool FUSED, int NT, int OUTM>
__global__ __launch_bounds__(256, 2)
void k_hmma(const __half* __restrict__ A, const __half* __restrict__ B,
            const float* __restrict__ bias, const int* __restrict__ mask,
            void* __restrict__ Outv,
            int Kpad, int NC, int OC, int P, int Nreal, int relu,
            const __half* __restrict__ Src, const int* __restrict__ selh,
            const int* __restrict__ selw, int IW, int ICp, int OW,
            int stride, int Klayer)
{
    extern __shared__ char smem[];
    const uint32_t sb = smem_u32(smem);
    int* s_base = (int*)(smem + 3*STAGE);
    const int tid = threadIdx.x, lane = tid & 31, warp = tid >> 5;
    const int wm = warp >> 1, wn = warp & 1;   // 4 x 2 warp grid; warp tile 32 x NT/2

    const long ld = (long)Kpad;
    const int l_row = tid >> 3, l_ch = tid & 7;
    const uint32_t l_soff = (uint32_t)(l_row*128 + ((l_ch ^ (l_row&7))<<4));
    const __half* Ag = A + (size_t)(blockIdx.y*128 + l_row) * ld + l_ch*8; // non-fused
    const __half* Bg = B + (size_t)(blockIdx.x*NT + l_row) * ld + l_ch*8;
    const long ld32 = 32*ld;

    if (FUSED){
        if (tid < 128){
            int n = blockIdx.y*128 + tid;
            if (n >= Nreal) n = Nreal - 1;            // clamp; masked in epilogue
            int b = n / P, p = n - b*P;
            int oy = p / OW, ox = p - oy*OW;
            int ph = oy*stride + (selh ? selh[p] : 0);
            int pw = ox*stride + (selw ? selw[p] : 0);
            s_base[tid] = (b*IW + ph)*IW + pw;        // square grid: IH==IW
        }
        __syncthreads();
    }

    auto loadA = [&](int cc, uint32_t sA){
        if (FUSED){
            int k = cc*64 + l_ch*8;
            uint32_t sz = (k < Klayer) ? 16u : 0u;
            long off = 0;
            if (sz){
                int tap = k / ICp, c = k - tap*ICp;
                int ky = tap/3, kx = tap - 3*ky;
                off = (long)(ky*IW + kx)*ICp + c;
            }
#pragma unroll
            for (int i=0;i<4;i++){
                int row = l_row + i*32;
                const __half* src = Src + (size_t)s_base[row]*ICp + off;
                cp16z(sA + l_soff + i*4096, src, sz);
            }
        } else {
#pragma unroll
            for (int i=0;i<4;i++) cp16(sA + l_soff + i*4096, Ag + cc*64 + i*ld32);
        }
    };
    auto loadB = [&](int cc, uint32_t sB){
#pragma unroll
        for (int i=0;i<NT/32;i++) cp16(sB + l_soff + i*4096, Bg + cc*64 + i*ld32);
    };

    // per-warp read geometry
    const uint32_t rowA = (uint32_t)((wm*32 + (lane & 15)) * 128);
    const uint32_t rowB = (uint32_t)((wn*(NT/2) + (lane & 15)) * 128);
    const uint32_t chbase = (uint32_t)(lane >> 4);
    const uint32_t chxor  = (uint32_t)(lane & 7);

    constexpr int NJ = NT/16;       // 8 (NT=128) or 4 (NT=64)
    constexpr int NB = NT/32;       // B ldmx4 count per ks
    float c[2][NJ][4];
#pragma unroll
    for (int i=0;i<2;i++)
#pragma unroll
        for (int j=0;j<NJ;j++)
#pragma unroll
            for (int k=0;k<4;k++) c[i][j][k] = 0.f;

    // prologue
    loadA(0, sb);           loadB(0, sb + 16384);           cp_commit();
    if (NC > 1){ loadA(1, sb + STAGE); loadB(1, sb + STAGE + 16384); }
    cp_commit();

#pragma unroll 1
    for (int cc = 0; cc < NC; cc++){
        cp_wait1();
        __syncthreads();
        if (cc + 2 < NC){
            int c2 = cc + 2;
            uint32_t sA = sb + (c2 % 3)*STAGE;
            loadA(c2, sA); loadB(c2, sA + 16384);
        }
        cp_commit();

        const uint32_t sA = sb + (cc % 3)*STAGE;
        const uint32_t sB = sA + 16384;
        const uint32_t aA0 = sA + rowA, aA1 = aA0 + 16*128;
        uint32_t aB[NB];
#pragma unroll
        for (int i=0;i<NB;i++) aB[i] = sB + rowB + i*16*128;

        uint32_t a[2][2][4], b[2][NB][4];
        {
            const uint32_t ch = (chbase ^ chxor) << 4;
            ldmx4(a[0][0], aA0 + ch); ldmx4(a[0][1], aA1 + ch);
#pragma unroll
            for (int i=0;i<NB;i++) ldmx4(b[0][i], aB[i] + ch);
        }
#pragma unroll
        for (int ks = 0; ks < 4; ks++){
            const int cur = ks & 1, nxt = cur ^ 1;
            if (ks < 3){
                const uint32_t ch = (((ks+1)*2 + chbase) ^ chxor) << 4;
                ldmx4(a[nxt][0], aA0 + ch); ldmx4(a[nxt][1], aA1 + ch);
#pragma unroll
                for (int i=0;i<NB;i++) ldmx4(b[nxt][i], aB[i] + ch);
            }
#pragma unroll
            for (int mi = 0; mi < 2; mi++)
#pragma unroll
                for (int nj = 0; nj < NJ; nj++)
                    mma_fp16(c[mi][nj], a[cur][mi],
                             b[cur][nj>>1][nj&1], b[cur][nj>>1][2+(nj&1)]);
        }
    }

    // ---- epilogue ----
    const int gm0 = blockIdx.y*128 + wm*32;
    const int oc0 = blockIdx.x*NT + wn*(NT/2);
#pragma unroll
    for (int mi = 0; mi < 2; mi++){
#pragma unroll
        for (int half = 0; half < 2; half++){
            int n = gm0 + mi*16 + half*8 + (lane >> 2);
            if (n >= Nreal) continue;
            int mk = 1;
            if (mask){ int p = n % P; mk = mask[p]; }
#pragma unroll
            for (int nj = 0; nj < NJ; nj++){
                int oc = oc0 + nj*8 + (lane & 3)*2;
                if (oc < OC){
                    float v0 = (mk ? c[mi][nj][half*2+0] : 0.f) + __ldg(&bias[oc]);
                    float v1 = (mk ? c[mi][nj][half*2+1] : 0.f) + __ldg(&bias[oc+1]);
                    if (relu){ v0 = fmaxf(v0, 0.f); v1 = fmaxf(v1, 0.f); }
                    if (OUTM == 1){
                        __half2* orow = (__half2*)((__half*)Outv + (size_t)n * OC + oc);
                        *orow = __floats2half2_rn(v0, v1);
                    } else if (OUTM == 0){
                        float2 v = {v0, v1};
                        *(float2*)((float*)Outv + (size_t)n * OC + oc) = v;
                    } else {   // fp32 NCHW flattened: Out[(b*OC + oc)*P + p]
                        int bb = n / P, p = n - bb*P;
                        float* o = (float*)Outv + (size_t)(bb*OC + oc)*P + p;
                        o[0] = v0;
                        o[P] = v1;   // oc+1 at stride P
                    }
                }
            }
        }
    }
}

// ======================= launch =======================
extern "C" void kernel_launch(void* const* d_in, const int* in_sizes, int n_in,
                              void* d_out, int out_size) {
    const float* x     = (const float*)d_in[0];
    const float* w1    = (const float*)d_in[1];
    const float* b1    = (const float*)d_in[2];
    const float* w2    = (const float*)d_in[3];
    const float* b2    = (const float*)d_in[4];
    const float* w3    = (const float*)d_in[5];
    const float* b3    = (const float*)d_in[6];
    const float* w4    = (const float*)d_in[7];
    const float* b4    = (const float*)d_in[8];
    const int*   selh1 = (const int*)d_in[9];
    const int*   selw1 = (const int*)d_in[10];
    const int*   mask1 = (const int*)d_in[11];
    const int*   selh2 = (const int*)d_in[12];
    const int*   selw2 = (const int*)d_in[13];
    const int*   mask2 = (const int*)d_in[14];
    const int*   selh3 = (const int*)d_in[15];
    const int*   selw3 = (const int*)d_in[16];
    const int*   mask3 = (const int*)d_in[17];

    float *pX;
    __half *pO1, *pO2, *pO3, *pA1, *pB1, *pB2, *pB3, *pB4;
    cudaGetSymbolAddress((void**)&pX,  g_X);
    cudaGetSymbolAddress((void**)&pO1, g_O1);
    cudaGetSymbolAddress((void**)&pO2, g_O2);
    cudaGetSymbolAddress((void**)&pO3, g_O3);
    cudaGetSymbolAddress((void**)&pA1, g_A1);
    cudaGetSymbolAddress((void**)&pB1, g_B1);
    cudaGetSymbolAddress((void**)&pB2, g_B2);
    cudaGetSymbolAddress((void**)&pB3, g_B3);
    cudaGetSymbolAddress((void**)&pB4, g_B4);

    cudaFuncSetAttribute((const void*)k_hmma<false,128,1>,
                         cudaFuncAttributeMaxDynamicSharedMemorySize, SMEM_HM);
    cudaFuncSetAttribute((const void*)k_hmma<true,128,1>,
                         cudaFuncAttributeMaxDynamicSharedMemorySize, SMEM_HM);
    cudaFuncSetAttribute((const void*)k_hmma<true,64,2>,
                         cudaFuncAttributeMaxDynamicSharedMemorySize, SMEM_HM);

    // x -> NHWC
    {
        int tot = 64 * 3 * 132 * 132;
        k_nchw2nhwc<<<(tot + 255) / 256, 256>>>(x, pX, 64, 3, 132, 132);
    }

    // ---- layer 1: im2col + GEMM (non-fused), fp16 out ----
    k_gather1<<<(270592 + 255) / 256, 256>>>(pX, pA1, selh1, selw1);
    k_wcvt<<<(256*64 + 255) / 256, 256>>>(w1, pB1, 200, 3, 27, 64, 256);
    k_hmma<false,128,1><<<dim3(2, 2114), 256, SMEM_HM>>>(
        pA1, pB1, b1, mask1, pO1, 64, 1, 200, 4225, 270400, 1,
        nullptr, nullptr, nullptr, 0, 0, 0, 0, 0);

    // ---- layer 2: fused gather GEMM, K=1800, Kpad=1856, NC=29, fp16 out ----
    {
        long wt = (long)512 * 1856;
        k_wcvt<<<(unsigned)((wt + 255) / 256), 256>>>(w2, pB2, 400, 200, 1800, 1856, 512);
        k_hmma<true,128,1><<<dim3(4, 482), 256, SMEM_HM>>>(
            nullptr, pB2, b2, mask2, pO2, 1856, 29, 400, 961, 61504, 1,
            pO1, selh2, selw2, 65, 200, 31, 2, 1800);
    }

    // ---- layer 3: fused gather GEMM, K=3600, Kpad=3648, NC=57, fp16 out ----
    {
        long wt = (long)896 * 3648;
        k_wcvt<<<(unsigned)((wt + 255) / 256), 256>>>(w3, pB3, 800, 400, 3600, 3648, 896);
        k_hmma<true,128,1><<<dim3(7, 114), 256, SMEM_HM>>>(
            nullptr, pB3, b3, mask3, pO3, 3648, 57, 800, 225, 14400, 1,
            pO2, selh3, selw3, 31, 400, 15, 2, 3600);
    }

    // ---- layer 4: fused dense GEMM, K=7200, Kpad=7232, NC=113, fp32 NCHW out ----
    {
        long wt = (long)64 * 7232;
        k_wcvt<<<(unsigned)((wt + 255) / 256), 256>>>(w4, pB4, 10, 800, 7200, 7232, 64);
        k_hmma<true,64,2><<<dim3(1, 85), 256, SMEM_HM>>>(
            nullptr, pB4, b4, nullptr, (float*)d_out, 7232, 113, 10, 169, 10816, 0,
            pO3, nullptr, nullptr, 15, 800, 13, 1, 7200);
    }
}

// round 10
// speedup vs baseline: 4.4744x; 1.0968x over previous
#include <cuda_runtime.h>
#include <cuda_fp16.h>
#include <cstdint>

#define DINLINE __device__ __forceinline__

// ======================= scratch (device globals) =======================
__device__ __align__(16) float  g_X [64*132*132*3];         // x NHWC fp32
__device__ __align__(16) __half g_O1[(size_t)64*65*65*200]; // L1 out fp16 NHWC
__device__ __align__(16) __half g_O2[(size_t)64*31*31*400]; // L2 out fp16 NHWC
__device__ __align__(16) __half g_O3[(size_t)64*15*15*800]; // L3 out fp16 NHWC
__device__ __align__(16) float  g_P4[(size_t)3*10880*64];   // L4 split-K partials

// L1 im2col: A1[Npad=270592][64]
__device__ __align__(16) __half g_A1[(size_t)270592*64];
// weights fp16 [OCpad][Kpad]
__device__ __align__(16) __half g_B1[(size_t)256*64];
__device__ __align__(16) __half g_B2[(size_t)512*1856];
__device__ __align__(16) __half g_B3[(size_t)896*3648];
__device__ __align__(16) __half g_B4[(size_t)64*7232];

// ======================= helpers =======================
DINLINE uint32_t smem_u32(const void* p){
    uint32_t a;
    asm("{ .reg .u64 t; cvta.to.shared.u64 t, %1; cvt.u32.u64 %0, t; }" : "=r"(a) : "l"(p));
    return a;
}
DINLINE void cp16(uint32_t dst, const void* src){
    asm volatile("cp.async.cg.shared.global [%0], [%1], 16;" :: "r"(dst), "l"(src));
}
DINLINE void cp16z(uint32_t dst, const void* src, uint32_t srcsize){
    asm volatile("cp.async.cg.shared.global [%0], [%1], 16, %2;" :: "r"(dst), "l"(src), "r"(srcsize));
}
DINLINE void cp_commit(){ asm volatile("cp.async.commit_group;" ::: "memory"); }
DINLINE void cp_wait1(){ asm volatile("cp.async.wait_group 1;" ::: "memory"); }

DINLINE void ldmx4(uint32_t r[4], uint32_t addr){
    asm volatile("ldmatrix.sync.aligned.m8n8.x4.shared.b16 {%0,%1,%2,%3}, [%4];"
        : "=r"(r[0]), "=r"(r[1]), "=r"(r[2]), "=r"(r[3]) : "r"(addr));
}
DINLINE void mma_fp16(float c[4], const uint32_t a[4], uint32_t b0, uint32_t b1){
    asm volatile("mma.sync.aligned.m16n8k16.row.col.f32.f16.f16.f32 "
        "{%0,%1,%2,%3}, {%4,%5,%6,%7}, {%8,%9}, {%0,%1,%2,%3};"
        : "+f"(c[0]), "+f"(c[1]), "+f"(c[2]), "+f"(c[3])
        : "r"(a[0]), "r"(a[1]), "r"(a[2]), "r"(a[3]), "r"(b0), "r"(b1));
}

// ======================= layout transforms =======================
__global__ void k_nchw2nhwc(const float* __restrict__ in, float* __restrict__ out,
                            int B, int C, int H, int W) {
    int idx = blockIdx.x * blockDim.x + threadIdx.x;
    if (idx >= B * C * H * W) return;
    int c = idx % C;
    int t = idx / C;
    int x = t % W; t /= W;
    int y = t % H; t /= H;
    out[idx] = in[((t * C + c) * H + y) * W + x];
}

// weights: fp16, [OCpad][Kpad], k = tap*IC + ic
__global__ void k_wcvt(const float* __restrict__ W, __half* __restrict__ Bw,
                       int OC, int IC, int Klayer, int Kpad, int OCpad)
{
    long idx = (long)blockIdx.x*blockDim.x + threadIdx.x;
    if (idx >= (long)OCpad * Kpad) return;
    int oc = (int)(idx / Kpad);
    int kk = (int)(idx - (long)oc*Kpad);
    __half out = __float2half_rn(0.f);
    if (oc < OC && kk < Klayer){
        int tap = kk/IC, c = kk - tap*IC;
        out = __float2half_rn(W[((size_t)oc*IC + c)*9 + tap]);
    }
    Bw[idx] = out;
}

// layer 1 gather: fp16, Kpad=64, cols [0:27) valid
__global__ void k_gather1(const float* __restrict__ X, __half* __restrict__ A,
                          const int* __restrict__ selh, const int* __restrict__ selw)
{
    int n = blockIdx.x*blockDim.x + threadIdx.x;
    if (n >= 270592) return;
    __half row[64];
#pragma unroll
    for (int i=0;i<64;i++) row[i] = __float2half_rn(0.f);
    if (n < 270400){
        int b = n / 4225, p = n - b*4225;
        int oy = p/65, ox = p - oy*65;
        int ph = oy*2 + selh[p], pw = ox*2 + selw[p];
        const float* base = X + ((size_t)(b*132+ph)*132 + pw)*3;
#pragma unroll
        for (int ky=0;ky<3;ky++){
#pragma unroll
            for (int t=0;t<9;t++){
                row[ky*9 + t] = __float2half_rn(base[ky*396 + t]);
            }
        }
    }
    uint4* dst = (uint4*)(A + (size_t)n*64);
    uint4* s = (uint4*)row;
#pragma unroll
    for (int i=0;i<8;i++) dst[i] = s[i];
}

// L4 combine: out[(b*10+oc)*169+p] = sum of 3 partials + bias
__global__ void k_out4(const float* __restrict__ P4, const float* __restrict__ bias,
                       float* __restrict__ out)
{
    int idx = blockIdx.x*blockDim.x + threadIdx.x;
    if (idx >= 108160) return;
    int n = idx / 10, oc = idx - n*10;
    const size_t ps = (size_t)10880*64;
    float v = P4[(size_t)n*64 + oc] + P4[ps + (size_t)n*64 + oc]
            + P4[2*ps + (size_t)n*64 + oc] + __ldg(&bias[oc]);
    int b = n / 169, p = n - b*169;
    out[(b*10 + oc)*169 + p] = v;
}

// ======================= HMMA GEMM =======================
// CTA tile 128(n) x NT(oc), BK=64, 256 threads (8 warps, 4x2), 2 CTAs/SM.
// 3-stage ring; fused im2col A-load with smem offset table (no div in hot loop).
// OUTM: 1 = fp16 NHWC, 3 = fp32 raw partial [n][64] with split-K over gridDim.z
static constexpr int STAGE = 32768;
static constexpr int SMEM_HM = 3 * STAGE + 512 + 3712;   // s_base + off table
static constexpr int SPLITC = 38;

template <bool FUSED, int NT, int OUTM>
__global__ __launch_bounds__(256, 2)
void k_hmma(const __half* __restrict__ A, const __half* __restrict__ B,
            const float* __restrict__ bias, const int* __restrict__ mask,
            void* __restrict__ Outv,
            int Kpad, int NC, int OC, int P, int Nreal, int relu,
            const __half* __restrict__ Src, const int* __restrict__ selh,
            const int* __restrict__ selw, int IW, int ICp, int OW,
            int stride, int Klayer)
{
    extern __shared__ char smem[];
    const uint32_t sb = smem_u32(smem);
    int* s_base = (int*)(smem + 3*STAGE);
    int* s_off  = (int*)(smem + 3*STAGE + 512);
    const int tid = threadIdx.x, lane = tid & 31, warp = tid >> 5;
    const int wm = warp >> 1, wn = warp & 1;   // 4 x 2 warp grid; warp tile 32 x NT/2

    const long ld = (long)Kpad;
    const int l_row = tid >> 3, l_ch = tid & 7;
    const uint32_t l_soff = (uint32_t)(l_row*128 + ((l_ch ^ (l_row&7))<<4));
    const __half* Ag = A + (size_t)(blockIdx.y*128 + l_row) * ld + l_ch*8; // non-fused
    const __half* Bg = B + (size_t)(blockIdx.x*NT + l_row) * ld + l_ch*8;
    const long ld32 = 32*ld;

    // split-K (OUTM==3): gridDim.z parts of SPLITC chunks
    const int cbase = (OUTM == 3) ? (int)blockIdx.z * SPLITC : 0;
    const int NCl   = (OUTM == 3) ? min(SPLITC, NC - cbase) : NC;

    if (FUSED){
        if (tid < 128){
            int n = blockIdx.y*128 + tid;
            if (n >= Nreal) n = Nreal - 1;            // clamp; masked in epilogue
            int b = n / P, p = n - b*P;
            int oy = p / OW, ox = p - oy*OW;
            int ph = oy*stride + (selh ? selh[p] : 0);
            int pw = ox*stride + (selw ? selw[p] : 0);
            s_base[tid] = (b*IW + ph)*IW + pw;        // square grid: IH==IW
        }
        // offset table: one entry per 8-wide K granule (Klayer % 8 == 0, IC % 8 == 0)
        for (int j = tid; j < (Klayer >> 3); j += 256){
            int k = j << 3;
            int tap = k / ICp, c = k - tap*ICp;
            int ky = tap/3, kx = tap - 3*ky;
            s_off[j] = (ky*IW + kx)*ICp + c;
        }
        __syncthreads();
    }

    auto loadA = [&](int chunk, uint32_t sA){
        if (FUSED){
            int j = chunk*8 + l_ch;
            int k = j << 3;
            uint32_t sz = (k < Klayer) ? 16u : 0u;
            long off = sz ? (long)s_off[j] : 0;
#pragma unroll
            for (int i=0;i<4;i++){
                int row = l_row + i*32;
                const __half* src = Src + (size_t)s_base[row]*ICp + off;
                cp16z(sA + l_soff + i*4096, src, sz);
            }
        } else {
#pragma unroll
            for (int i=0;i<4;i++) cp16(sA + l_soff + i*4096, Ag + chunk*64 + i*ld32);
        }
    };
    auto loadB = [&](int chunk, uint32_t sB){
#pragma unroll
        for (int i=0;i<NT/32;i++) cp16(sB + l_soff + i*4096, Bg + chunk*64 + i*ld32);
    };

    // per-warp read geometry
    const uint32_t rowA = (uint32_t)((wm*32 + (lane & 15)) * 128);
    const uint32_t rowB = (uint32_t)((wn*(NT/2) + (lane & 15)) * 128);
    const uint32_t chbase = (uint32_t)(lane >> 4);
    const uint32_t chxor  = (uint32_t)(lane & 7);

    constexpr int NJ = NT/16;
    constexpr int NB = NT/32;
    float c[2][NJ][4];
#pragma unroll
    for (int i=0;i<2;i++)
#pragma unroll
        for (int j=0;j<NJ;j++)
#pragma unroll
            for (int k=0;k<4;k++) c[i][j][k] = 0.f;

    // prologue
    loadA(cbase, sb);       loadB(cbase, sb + 16384);       cp_commit();
    if (NCl > 1){ loadA(cbase+1, sb + STAGE); loadB(cbase+1, sb + STAGE + 16384); }
    cp_commit();

#pragma unroll 1
    for (int cc = 0; cc < NCl; cc++){
        cp_wait1();
        __syncthreads();
        if (cc + 2 < NCl){
            uint32_t sA = sb + ((cc+2) % 3)*STAGE;
            loadA(cbase+cc+2, sA); loadB(cbase+cc+2, sA + 16384);
        }
        cp_commit();

        const uint32_t sA = sb + (cc % 3)*STAGE;
        const uint32_t sB = sA + 16384;
        const uint32_t aA0 = sA + rowA, aA1 = aA0 + 16*128;
        uint32_t aB[NB];
#pragma unroll
        for (int i=0;i<NB;i++) aB[i] = sB + rowB + i*16*128;

        uint32_t a[2][2][4], b[2][NB][4];
        {
            const uint32_t ch = (chbase ^ chxor) << 4;
            ldmx4(a[0][0], aA0 + ch); ldmx4(a[0][1], aA1 + ch);
#pragma unroll
            for (int i=0;i<NB;i++) ldmx4(b[0][i], aB[i] + ch);
        }
#pragma unroll
        for (int ks = 0; ks < 4; ks++){
            const int cur = ks & 1, nxt = cur ^ 1;
            if (ks < 3){
                const uint32_t ch = (((ks+1)*2 + chbase) ^ chxor) << 4;
                ldmx4(a[nxt][0], aA0 + ch); ldmx4(a[nxt][1], aA1 + ch);
#pragma unroll
                for (int i=0;i<NB;i++) ldmx4(b[nxt][i], aB[i] + ch);
            }
#pragma unroll
            for (int mi = 0; mi < 2; mi++)
#pragma unroll
                for (int nj = 0; nj < NJ; nj++)
                    mma_fp16(c[mi][nj], a[cur][mi],
                             b[cur][nj>>1][nj&1], b[cur][nj>>1][2+(nj&1)]);
        }
    }

    // ---- epilogue ----
    const int gm0 = blockIdx.y*128 + wm*32;
    const int oc0 = blockIdx.x*NT + wn*(NT/2);
#pragma unroll
    for (int mi = 0; mi < 2; mi++){
#pragma unroll
        for (int half = 0; half < 2; half++){
            int n = gm0 + mi*16 + half*8 + (lane >> 2);
            if (n >= Nreal) continue;
            int mk = 1;
            if (OUTM != 3 && mask){ int p = n % P; mk = mask[p]; }
#pragma unroll
            for (int nj = 0; nj < NJ; nj++){
                int oc = oc0 + nj*8 + (lane & 3)*2;
                if (oc < OC || OUTM == 3){
                    if (OUTM == 3){
                        // raw fp32 partial, [n][64], per-part buffer
                        float* o = (float*)Outv + (size_t)blockIdx.z*10880*64
                                 + (size_t)n*64 + oc;
                        float2 v = {c[mi][nj][half*2+0], c[mi][nj][half*2+1]};
                        *(float2*)o = v;
                    } else {
                        float v0 = (mk ? c[mi][nj][half*2+0] : 0.f) + __ldg(&bias[oc]);
                        float v1 = (mk ? c[mi][nj][half*2+1] : 0.f) + __ldg(&bias[oc+1]);
                        if (relu){ v0 = fmaxf(v0, 0.f); v1 = fmaxf(v1, 0.f); }
                        __half2* orow = (__half2*)((__half*)Outv + (size_t)n * OC + oc);
                        *orow = __floats2half2_rn(v0, v1);
                    }
                }
            }
        }
    }
}

// ======================= launch =======================
extern "C" void kernel_launch(void* const* d_in, const int* in_sizes, int n_in,
                              void* d_out, int out_size) {
    const float* x     = (const float*)d_in[0];
    const float* w1    = (const float*)d_in[1];
    const float* b1    = (const float*)d_in[2];
    const float* w2    = (const float*)d_in[3];
    const float* b2    = (const float*)d_in[4];
    const float* w3    = (const float*)d_in[5];
    const float* b3    = (const float*)d_in[6];
    const float* w4    = (const float*)d_in[7];
    const float* b4    = (const float*)d_in[8];
    const int*   selh1 = (const int*)d_in[9];
    const int*   selw1 = (const int*)d_in[10];
    const int*   mask1 = (const int*)d_in[11];
    const int*   selh2 = (const int*)d_in[12];
    const int*   selw2 = (const int*)d_in[13];
    const int*   mask2 = (const int*)d_in[14];
    const int*   selh3 = (const int*)d_in[15];
    const int*   selw3 = (const int*)d_in[16];
    const int*   mask3 = (const int*)d_in[17];

    float *pX, *pP4;
    __half *pO1, *pO2, *pO3, *pA1, *pB1, *pB2, *pB3, *pB4;
    cudaGetSymbolAddress((void**)&pX,  g_X);
    cudaGetSymbolAddress((void**)&pO1, g_O1);
    cudaGetSymbolAddress((void**)&pO2, g_O2);
    cudaGetSymbolAddress((void**)&pO3, g_O3);
    cudaGetSymbolAddress((void**)&pP4, g_P4);
    cudaGetSymbolAddress((void**)&pA1, g_A1);
    cudaGetSymbolAddress((void**)&pB1, g_B1);
    cudaGetSymbolAddress((void**)&pB2, g_B2);
    cudaGetSymbolAddress((void**)&pB3, g_B3);
    cudaGetSymbolAddress((void**)&pB4, g_B4);

    cudaFuncSetAttribute((const void*)k_hmma<false,128,1>,
                         cudaFuncAttributeMaxDynamicSharedMemorySize, SMEM_HM);
    cudaFuncSetAttribute((const void*)k_hmma<true,128,1>,
                         cudaFuncAttributeMaxDynamicSharedMemorySize, SMEM_HM);
    cudaFuncSetAttribute((const void*)k_hmma<true,64,3>,
                         cudaFuncAttributeMaxDynamicSharedMemorySize, SMEM_HM);

    // x -> NHWC
    {
        int tot = 64 * 3 * 132 * 132;
        k_nchw2nhwc<<<(tot + 255) / 256, 256>>>(x, pX, 64, 3, 132, 132);
    }

    // ---- layer 1: im2col + GEMM (non-fused), fp16 out ----
    k_gather1<<<(270592 + 255) / 256, 256>>>(pX, pA1, selh1, selw1);
    k_wcvt<<<(256*64 + 255) / 256, 256>>>(w1, pB1, 200, 3, 27, 64, 256);
    k_hmma<false,128,1><<<dim3(2, 2114), 256, SMEM_HM>>>(
        pA1, pB1, b1, mask1, pO1, 64, 1, 200, 4225, 270400, 1,
        nullptr, nullptr, nullptr, 0, 0, 0, 0, 0);

    // ---- layer 2: fused gather GEMM, K=1800, Kpad=1856, NC=29, fp16 out ----
    {
        long wt = (long)512 * 1856;
        k_wcvt<<<(unsigned)((wt + 255) / 256), 256>>>(w2, pB2, 400, 200, 1800, 1856, 512);
        k_hmma<true,128,1><<<dim3(4, 482), 256, SMEM_HM>>>(
            nullptr, pB2, b2, mask2, pO2, 1856, 29, 400, 961, 61504, 1,
            pO1, selh2, selw2, 65, 200, 31, 2, 1800);
    }

    // ---- layer 3: fused gather GEMM, K=3600, Kpad=3648, NC=57, fp16 out ----
    {
        long wt = (long)896 * 3648;
        k_wcvt<<<(unsigned)((wt + 255) / 256), 256>>>(w3, pB3, 800, 400, 3600, 3648, 896);
        k_hmma<true,128,1><<<dim3(7, 114), 256, SMEM_HM>>>(
            nullptr, pB3, b3, mask3, pO3, 3648, 57, 800, 225, 14400, 1,
            pO2, selh3, selw3, 31, 400, 15, 2, 3600);
    }

    // ---- layer 4: fused dense GEMM, split-K x3 partials + combine ----
    {
        long wt = (long)64 * 7232;
        k_wcvt<<<(unsigned)((wt + 255) / 256), 256>>>(w4, pB4, 10, 800, 7200, 7232, 64);
        k_hmma<true,64,3><<<dim3(1, 85, 3), 256, SMEM_HM>>>(
            nullptr, pB4, b4, nullptr, pP4, 7232, 113, 10, 169, 10816, 0,
            pO3, nullptr, nullptr, 15, 800, 13, 1, 7200);
        k_out4<<<(108160 + 255) / 256, 256>>>(pP4, b4, (float*)d_out);
    }
}

// round 11
// speedup vs baseline: 4.6760x; 1.0451x over previous
#include <cuda_runtime.h>
#include <cuda_fp16.h>
#include <cstdint>

#define DINLINE __device__ __forceinline__

// ======================= scratch (device globals) =======================
__device__ __align__(16) __half g_O1[(size_t)64*65*65*200]; // L1 out fp16 NHWC
__device__ __align__(16) __half g_O2[(size_t)64*31*31*400]; // L2 out fp16 NHWC
__device__ __align__(16) __half g_O3[(size_t)64*15*15*800]; // L3 out fp16 NHWC
__device__ __align__(16) float  g_P4[(size_t)3*10880*64];   // L4 split-K partials

// L1 im2col: A1[Npad=270592][64]
__device__ __align__(16) __half g_A1[(size_t)270592*64];
// weights fp16 [OCpad][Kpad]
__device__ __align__(16) __half g_B1[(size_t)256*64];
__device__ __align__(16) __half g_B2[(size_t)512*1856];
__device__ __align__(16) __half g_B3[(size_t)896*3648];
__device__ __align__(16) __half g_B4[(size_t)64*7232];

// ======================= helpers =======================
DINLINE uint32_t smem_u32(const void* p){
    uint32_t a;
    asm("{ .reg .u64 t; cvta.to.shared.u64 t, %1; cvt.u32.u64 %0, t; }" : "=r"(a) : "l"(p));
    return a;
}
DINLINE void cp16(uint32_t dst, const void* src){
    asm volatile("cp.async.cg.shared.global [%0], [%1], 16;" :: "r"(dst), "l"(src));
}
DINLINE void cp16z(uint32_t dst, const void* src, uint32_t srcsize){
    asm volatile("cp.async.cg.shared.global [%0], [%1], 16, %2;" :: "r"(dst), "l"(src), "r"(srcsize));
}
DINLINE void cp_commit(){ asm volatile("cp.async.commit_group;" ::: "memory"); }
DINLINE void cp_wait1(){ asm volatile("cp.async.wait_group 1;" ::: "memory"); }

DINLINE void ldmx4(uint32_t r[4], uint32_t addr){
    asm volatile("ldmatrix.sync.aligned.m8n8.x4.shared.b16 {%0,%1,%2,%3}, [%4];"
        : "=r"(r[0]), "=r"(r[1]), "=r"(r[2]), "=r"(r[3]) : "r"(addr));
}
DINLINE void mma_fp16(float c[4], const uint32_t a[4], uint32_t b0, uint32_t b1){
    asm volatile("mma.sync.aligned.m16n8k16.row.col.f32.f16.f16.f32 "
        "{%0,%1,%2,%3}, {%4,%5,%6,%7}, {%8,%9}, {%0,%1,%2,%3};"
        : "+f"(c[0]), "+f"(c[1]), "+f"(c[2]), "+f"(c[3])
        : "r"(a[0]), "r"(a[1]), "r"(a[2]), "r"(a[3]), "r"(b0), "r"(b1));
}

// ======================= transforms =======================
// weights: fp16, [OCpad][Kpad], k = tap*IC + ic
__global__ void k_wcvt(const float* __restrict__ W, __half* __restrict__ Bw,
                       int OC, int IC, int Klayer, int Kpad, int OCpad)
{
    long idx = (long)blockIdx.x*blockDim.x + threadIdx.x;
    if (idx >= (long)OCpad * Kpad) return;
    int oc = (int)(idx / Kpad);
    int kk = (int)(idx - (long)oc*Kpad);
    __half out = __float2half_rn(0.f);
    if (oc < OC && kk < Klayer){
        int tap = kk/IC, c = kk - tap*IC;
        out = __float2half_rn(W[((size_t)oc*IC + c)*9 + tap]);
    }
    Bw[idx] = out;
}

// layer 1 gather directly from x NCHW: fp16, Kpad=64, cols [0:27) valid
__global__ void k_gather1(const float* __restrict__ X, __half* __restrict__ A,
                          const int* __restrict__ selh, const int* __restrict__ selw)
{
    int n = blockIdx.x*blockDim.x + threadIdx.x;
    if (n >= 270592) return;
    __half row[64];
#pragma unroll
    for (int i=0;i<64;i++) row[i] = __float2half_rn(0.f);
    if (n < 270400){
        int b = n / 4225, p = n - b*4225;
        int oy = p/65, ox = p - oy*65;
        int ph = oy*2 + selh[p], pw = ox*2 + selw[p];
        const float* xb = X + (size_t)b*3*132*132 + ph*132 + pw;
#pragma unroll
        for (int ic=0; ic<3; ic++){
#pragma unroll
            for (int ky=0; ky<3; ky++){
#pragma unroll
                for (int kx=0; kx<3; kx++){
                    float v = xb[(size_t)ic*132*132 + ky*132 + kx];
                    row[(ky*3 + kx)*3 + ic] = __float2half_rn(v);
                }
            }
        }
    }
    uint4* dst = (uint4*)(A + (size_t)n*64);
    uint4* s = (uint4*)row;
#pragma unroll
    for (int i=0;i<8;i++) dst[i] = s[i];
}

// L4 combine: out[(b*10+oc)*169+p] = sum of 3 partials + bias
__global__ void k_out4(const float* __restrict__ P4, const float* __restrict__ bias,
                       float* __restrict__ out)
{
    int idx = blockIdx.x*blockDim.x + threadIdx.x;
    if (idx >= 108160) return;
    int n = idx / 10, oc = idx - n*10;
    const size_t ps = (size_t)10880*64;
    float v = P4[(size_t)n*64 + oc] + P4[ps + (size_t)n*64 + oc]
            + P4[2*ps + (size_t)n*64 + oc] + __ldg(&bias[oc]);
    int b = n / 169, p = n - b*169;
    out[(b*10 + oc)*169 + p] = v;
}

// ======================= persistent L1 GEMM =======================
// B tile (16KB) resident; 3-stage A ring (16KB each); each CTA streams ~14 n-blocks.
// grid (2, 148), 256 thr, 2 CTAs/SM. K=64 (1 chunk), OC=200, mask+bias+relu fp16 out.
static constexpr int SMEM_L1 = 16384 * 4;

__global__ __launch_bounds__(256, 2)
void k_hmma1(const __half* __restrict__ A, const __half* __restrict__ Bw,
             const float* __restrict__ bias, const int* __restrict__ mask,
             __half* __restrict__ Out)
{
    extern __shared__ char smem[];
    const uint32_t sb = smem_u32(smem);
    const int tid = threadIdx.x, lane = tid & 31, warp = tid >> 5;
    const int wm = warp >> 1, wn = warp & 1;

    const int l_row = tid >> 3, l_ch = tid & 7;
    const uint32_t l_soff = (uint32_t)(l_row*128 + ((l_ch ^ (l_row&7))<<4));

    // B once: rows [x*128, x*128+128) of g_B1[256][64]
    {
        const __half* Bg = Bw + (size_t)(blockIdx.x*128 + l_row)*64 + l_ch*8;
#pragma unroll
        for (int i=0;i<4;i++) cp16(sb + l_soff + i*4096, Bg + i*32*64);
    }

    const int NBLK = 2114, STEP = gridDim.y;
    auto loadA = [&](int it){
        int nb = blockIdx.y + it*STEP;
        if (nb >= NBLK) return;
        const __half* Ag = A + ((size_t)nb*128 + l_row)*64 + l_ch*8;
        uint32_t sA = sb + 16384 + (it%3)*16384;
#pragma unroll
        for (int j=0;j<4;j++) cp16(sA + l_soff + j*4096, Ag + j*32*64);
    };

    loadA(0); cp_commit();     // group 0: B + A(0)
    loadA(1); cp_commit();     // group 1: A(1)

    const uint32_t rowA = (uint32_t)((wm*32 + (lane & 15)) * 128);
    const uint32_t rowB = (uint32_t)((wn*64 + (lane & 15)) * 128);
    const uint32_t chbase = (uint32_t)(lane >> 4);
    const uint32_t chxor  = (uint32_t)(lane & 7);
    const uint32_t sB = sb;
    uint32_t aB[4];
#pragma unroll
    for (int i=0;i<4;i++) aB[i] = sB + rowB + i*16*128;

    const int niter = (NBLK - blockIdx.y + STEP - 1) / STEP;
#pragma unroll 1
    for (int it = 0; it < niter; it++){
        cp_wait1();
        __syncthreads();
        loadA(it+2); cp_commit();

        const uint32_t sA = sb + 16384 + (it%3)*16384;
        const uint32_t aA0 = sA + rowA, aA1 = aA0 + 16*128;

        float c[2][8][4];
#pragma unroll
        for (int i=0;i<2;i++)
#pragma unroll
            for (int j=0;j<8;j++)
#pragma unroll
                for (int k=0;k<4;k++) c[i][j][k] = 0.f;

        uint32_t a[2][2][4], b[2][4][4];
        {
            const uint32_t ch = (chbase ^ chxor) << 4;
            ldmx4(a[0][0], aA0 + ch); ldmx4(a[0][1], aA1 + ch);
#pragma unroll
            for (int i=0;i<4;i++) ldmx4(b[0][i], aB[i] + ch);
        }
#pragma unroll
        for (int ks = 0; ks < 4; ks++){
            const int cur = ks & 1, nxt = cur ^ 1;
            if (ks < 3){
                const uint32_t ch = (((ks+1)*2 + chbase) ^ chxor) << 4;
                ldmx4(a[nxt][0], aA0 + ch); ldmx4(a[nxt][1], aA1 + ch);
#pragma unroll
                for (int i=0;i<4;i++) ldmx4(b[nxt][i], aB[i] + ch);
            }
#pragma unroll
            for (int mi = 0; mi < 2; mi++)
#pragma unroll
                for (int nj = 0; nj < 8; nj++)
                    mma_fp16(c[mi][nj], a[cur][mi],
                             b[cur][nj>>1][nj&1], b[cur][nj>>1][2+(nj&1)]);
        }

        // epilogue
        const int nb = blockIdx.y + it*STEP;
        const int gm0 = nb*128 + wm*32;
        const int oc0 = blockIdx.x*128 + wn*64;
#pragma unroll
        for (int mi = 0; mi < 2; mi++){
#pragma unroll
            for (int half = 0; half < 2; half++){
                int n = gm0 + mi*16 + half*8 + (lane >> 2);
                if (n >= 270400) continue;
                int p = n % 4225;
                int mk = mask[p];
#pragma unroll
                for (int nj = 0; nj < 8; nj++){
                    int oc = oc0 + nj*8 + (lane & 3)*2;
                    if (oc < 200){
                        float v0 = (mk ? c[mi][nj][half*2+0] : 0.f) + __ldg(&bias[oc]);
                        float v1 = (mk ? c[mi][nj][half*2+1] : 0.f) + __ldg(&bias[oc+1]);
                        v0 = fmaxf(v0, 0.f); v1 = fmaxf(v1, 0.f);
                        __half2* orow = (__half2*)(Out + (size_t)n * 200 + oc);
                        *orow = __floats2half2_rn(v0, v1);
                    }
                }
            }
        }
    }
}

// ======================= HMMA GEMM (L2/L3/L4) =======================
static constexpr int STAGE = 32768;
static constexpr int SMEM_HM = 3 * STAGE + 512 + 3712;
static constexpr int SPLITC = 38;

template <int NT, int OUTM>   // OUTM: 1=fp16 NHWC, 3=fp32 split-K partials
__global__ __launch_bounds__(256, 2)
void k_hmma(const __half* __restrict__ B,
            const float* __restrict__ bias, const int* __restrict__ mask,
            void* __restrict__ Outv,
            int Kpad, int NC, int OC, int P, int Nreal, int relu,
            const __half* __restrict__ Src, const int* __restrict__ selh,
            const int* __restrict__ selw, int IW, int ICp, int OW,
            int stride, int Klayer)
{
    extern __shared__ char smem[];
    const uint32_t sb = smem_u32(smem);
    int* s_base = (int*)(smem + 3*STAGE);
    int* s_off  = (int*)(smem + 3*STAGE + 512);
    const int tid = threadIdx.x, lane = tid & 31, warp = tid >> 5;
    const int wm = warp >> 1, wn = warp & 1;

    const long ld = (long)Kpad;
    const int l_row = tid >> 3, l_ch = tid & 7;
    const uint32_t l_soff = (uint32_t)(l_row*128 + ((l_ch ^ (l_row&7))<<4));
    const __half* Bg = B + (size_t)(blockIdx.x*NT + l_row) * ld + l_ch*8;
    const long ld32 = 32*ld;

    const int cbase = (OUTM == 3) ? (int)blockIdx.z * SPLITC : 0;
    const int NCl   = (OUTM == 3) ? min(SPLITC, NC - cbase) : NC;

    if (tid < 128){
        int n = blockIdx.y*128 + tid;
        if (n >= Nreal) n = Nreal - 1;
        int b = n / P, p = n - b*P;
        int oy = p / OW, ox = p - oy*OW;
        int ph = oy*stride + (selh ? selh[p] : 0);
        int pw = ox*stride + (selw ? selw[p] : 0);
        s_base[tid] = (b*IW + ph)*IW + pw;
    }
    for (int j = tid; j < (Klayer >> 3); j += 256){
        int k = j << 3;
        int tap = k / ICp, c = k - tap*ICp;
        int ky = tap/3, kx = tap - 3*ky;
        s_off[j] = (ky*IW + kx)*ICp + c;
    }
    __syncthreads();

    auto loadA = [&](int chunk, uint32_t sA){
        int j = chunk*8 + l_ch;
        int k = j << 3;
        uint32_t sz = (k < Klayer) ? 16u : 0u;
        long off = sz ? (long)s_off[j] : 0;
#pragma unroll
        for (int i=0;i<4;i++){
            int row = l_row + i*32;
            const __half* src = Src + (size_t)s_base[row]*ICp + off;
            cp16z(sA + l_soff + i*4096, src, sz);
        }
    };
    auto loadB = [&](int chunk, uint32_t sB){
#pragma unroll
        for (int i=0;i<NT/32;i++) cp16(sB + l_soff + i*4096, Bg + chunk*64 + i*ld32);
    };

    const uint32_t rowA = (uint32_t)((wm*32 + (lane & 15)) * 128);
    const uint32_t rowB = (uint32_t)((wn*(NT/2) + (lane & 15)) * 128);
    const uint32_t chbase = (uint32_t)(lane >> 4);
    const uint32_t chxor  = (uint32_t)(lane & 7);

    constexpr int NJ = NT/16;
    constexpr int NB = NT/32;
    float c[2][NJ][4];
#pragma unroll
    for (int i=0;i<2;i++)
#pragma unroll
        for (int j=0;j<NJ;j++)
#pragma unroll
            for (int k=0;k<4;k++) c[i][j][k] = 0.f;

    loadA(cbase, sb);       loadB(cbase, sb + 16384);       cp_commit();
    if (NCl > 1){ loadA(cbase+1, sb + STAGE); loadB(cbase+1, sb + STAGE + 16384); }
    cp_commit();

#pragma unroll 1
    for (int cc = 0; cc < NCl; cc++){
        cp_wait1();
        __syncthreads();
        if (cc + 2 < NCl){
            uint32_t sA = sb + ((cc+2) % 3)*STAGE;
            loadA(cbase+cc+2, sA); loadB(cbase+cc+2, sA + 16384);
        }
        cp_commit();

        const uint32_t sA = sb + (cc % 3)*STAGE;
        const uint32_t sB = sA + 16384;
        const uint32_t aA0 = sA + rowA, aA1 = aA0 + 16*128;
        uint32_t aB[NB];
#pragma unroll
        for (int i=0;i<NB;i++) aB[i] = sB + rowB + i*16*128;

        uint32_t a[2][2][4], b[2][NB][4];
        {
            const uint32_t ch = (chbase ^ chxor) << 4;
            ldmx4(a[0][0], aA0 + ch); ldmx4(a[0][1], aA1 + ch);
#pragma unroll
            for (int i=0;i<NB;i++) ldmx4(b[0][i], aB[i] + ch);
        }
#pragma unroll
        for (int ks = 0; ks < 4; ks++){
            const int cur = ks & 1, nxt = cur ^ 1;
            if (ks < 3){
                const uint32_t ch = (((ks+1)*2 + chbase) ^ chxor) << 4;
                ldmx4(a[nxt][0], aA0 + ch); ldmx4(a[nxt][1], aA1 + ch);
#pragma unroll
                for (int i=0;i<NB;i++) ldmx4(b[nxt][i], aB[i] + ch);
            }
#pragma unroll
            for (int mi = 0; mi < 2; mi++)
#pragma unroll
                for (int nj = 0; nj < NJ; nj++)
                    mma_fp16(c[mi][nj], a[cur][mi],
                             b[cur][nj>>1][nj&1], b[cur][nj>>1][2+(nj&1)]);
        }
    }

    const int gm0 = blockIdx.y*128 + wm*32;
    const int oc0 = blockIdx.x*NT + wn*(NT/2);
#pragma unroll
    for (int mi = 0; mi < 2; mi++){
#pragma unroll
        for (int half = 0; half < 2; half++){
            int n = gm0 + mi*16 + half*8 + (lane >> 2);
            if (n >= Nreal) continue;
            int mk = 1;
            if (OUTM != 3 && mask){ int p = n % P; mk = mask[p]; }
#pragma unroll
            for (int nj = 0; nj < NJ; nj++){
                int oc = oc0 + nj*8 + (lane & 3)*2;
                if (oc < OC || OUTM == 3){
                    if (OUTM == 3){
                        float* o = (float*)Outv + (size_t)blockIdx.z*10880*64
                                 + (size_t)n*64 + oc;
                        float2 v = {c[mi][nj][half*2+0], c[mi][nj][half*2+1]};
                        *(float2*)o = v;
                    } else {
                        float v0 = (mk ? c[mi][nj][half*2+0] : 0.f) + __ldg(&bias[oc]);
                        float v1 = (mk ? c[mi][nj][half*2+1] : 0.f) + __ldg(&bias[oc+1]);
                        if (relu){ v0 = fmaxf(v0, 0.f); v1 = fmaxf(v1, 0.f); }
                        __half2* orow = (__half2*)((__half*)Outv + (size_t)n * OC + oc);
                        *orow = __floats2half2_rn(v0, v1);
                    }
                }
            }
        }
    }
}

// ======================= launch =======================
extern "C" void kernel_launch(void* const* d_in, const int* in_sizes, int n_in,
                              void* d_out, int out_size) {
    const float* x     = (const float*)d_in[0];
    const float* w1    = (const float*)d_in[1];
    const float* b1    = (const float*)d_in[2];
    const float* w2    = (const float*)d_in[3];
    const float* b2    = (const float*)d_in[4];
    const float* w3    = (const float*)d_in[5];
    const float* b3    = (const float*)d_in[6];
    const float* w4    = (const float*)d_in[7];
    const float* b4    = (const float*)d_in[8];
    const int*   selh1 = (const int*)d_in[9];
    const int*   selw1 = (const int*)d_in[10];
    const int*   mask1 = (const int*)d_in[11];
    const int*   selh2 = (const int*)d_in[12];
    const int*   selw2 = (const int*)d_in[13];
    const int*   mask2 = (const int*)d_in[14];
    const int*   selh3 = (const int*)d_in[15];
    const int*   selw3 = (const int*)d_in[16];
    const int*   mask3 = (const int*)d_in[17];

    float *pP4;
    __half *pO1, *pO2, *pO3, *pA1, *pB1, *pB2, *pB3, *pB4;
    cudaGetSymbolAddress((void**)&pO1, g_O1);
    cudaGetSymbolAddress((void**)&pO2, g_O2);
    cudaGetSymbolAddress((void**)&pO3, g_O3);
    cudaGetSymbolAddress((void**)&pP4, g_P4);
    cudaGetSymbolAddress((void**)&pA1, g_A1);
    cudaGetSymbolAddress((void**)&pB1, g_B1);
    cudaGetSymbolAddress((void**)&pB2, g_B2);
    cudaGetSymbolAddress((void**)&pB3, g_B3);
    cudaGetSymbolAddress((void**)&pB4, g_B4);

    cudaFuncSetAttribute((const void*)k_hmma1,
                         cudaFuncAttributeMaxDynamicSharedMemorySize, SMEM_L1);
    cudaFuncSetAttribute((const void*)k_hmma<128,1>,
                         cudaFuncAttributeMaxDynamicSharedMemorySize, SMEM_HM);
    cudaFuncSetAttribute((const void*)k_hmma<64,3>,
                         cudaFuncAttributeMaxDynamicSharedMemorySize, SMEM_HM);

    // ---- layer 1: gather from x NCHW + persistent-B GEMM ----
    k_gather1<<<(270592 + 255) / 256, 256>>>(x, pA1, selh1, selw1);
    k_wcvt<<<(256*64 + 255) / 256, 256>>>(w1, pB1, 200, 3, 27, 64, 256);
    k_hmma1<<<dim3(2, 148), 256, SMEM_L1>>>(pA1, pB1, b1, mask1, pO1);

    // ---- layer 2: fused gather GEMM, K=1800, Kpad=1856, NC=29, fp16 out ----
    {
        long wt = (long)512 * 1856;
        k_wcvt<<<(unsigned)((wt + 255) / 256), 256>>>(w2, pB2, 400, 200, 1800, 1856, 512);
        k_hmma<128,1><<<dim3(4, 482), 256, SMEM_HM>>>(
            pB2, b2, mask2, pO2, 1856, 29, 400, 961, 61504, 1,
            pO1, selh2, selw2, 65, 200, 31, 2, 1800);
    }

    // ---- layer 3: fused gather GEMM, K=3600, Kpad=3648, NC=57, fp16 out ----
    {
        long wt = (long)896 * 3648;
        k_wcvt<<<(unsigned)((wt + 255) / 256), 256>>>(w3, pB3, 800, 400, 3600, 3648, 896);
        k_hmma<128,1><<<dim3(7, 114), 256, SMEM_HM>>>(
            pB3, b3, mask3, pO3, 3648, 57, 800, 225, 14400, 1,
            pO2, selh3, selw3, 31, 400, 15, 2, 3600);
    }

    // ---- layer 4: fused dense GEMM, split-K x3 partials + combine ----
    {
        long wt = (long)64 * 7232;
        k_wcvt<<<(unsigned)((wt + 255) / 256), 256>>>(w4, pB4, 10, 800, 7200, 7232, 64);
        k_hmma<64,3><<<dim3(1, 85, 3), 256, SMEM_HM>>>(
            pB4, b4, nullptr, pP4, 7232, 113, 10, 169, 10816, 0,
            pO3, nullptr, nullptr, 15, 800, 13, 1, 7200);
        k_out4<<<(108160 + 255) / 256, 256>>>(pP4, b4, (float*)d_out);
    }
}